// round 1
// baseline (speedup 1.0000x reference)
#include <cuda_runtime.h>
#include <math.h>

#define SEQL   2048
#define BSZ    2
#define ROWS   (BSZ*SEQL)          // 4096
#define DIMX   2048
#define QLORA  1536
#define KVLORA 512
#define NHEADS 16
#define QKHD   192                 // 128 nope + 64 rope
#define NOPE_D 128
#define ROPE_D 64
#define VHD    128

// ---------------- scratch (static device globals; no allocation) ----------------
__device__ float g_qa [ROWS*QLORA];                 // 4096x1536
__device__ float g_qb [ROWS*(NHEADS*QKHD)];         // 4096x3072
__device__ float g_kva[ROWS*(KVLORA+ROPE_D)];       // 4096x576
__device__ float g_kvb[ROWS*(NHEADS*(NOPE_D+VHD))]; // 4096x4096
__device__ float g_att[ROWS*(NHEADS*VHD)];          // 4096x2048

// ---------------- GEMM: C[M,N] = A[M,K] @ W[N,K]^T + bias ----------------
// A row-major (lda), W row-major (ldw) -> "NT" layout, both K-contiguous.
__global__ __launch_bounds__(256)
void gemm_nt_bias(const float* __restrict__ A, int lda,
                  const float* __restrict__ W, int ldw,
                  const float* __restrict__ bias,
                  float* __restrict__ C, int ldc,
                  int M, int N, int K)
{
    __shared__ float As[8][128];
    __shared__ float Bs[8][128];

    const int bm = blockIdx.y * 128;
    const int bn = blockIdx.x * 128;
    const int tid = threadIdx.x;
    const int tx = tid & 15;
    const int ty = tid >> 4;

    const int lrow = tid >> 1;         // 0..127
    const int lk   = (tid & 1) << 2;   // 0 or 4

    float acc[8][8];
#pragma unroll
    for (int i = 0; i < 8; i++)
#pragma unroll
        for (int j = 0; j < 8; j++) acc[i][j] = 0.f;

    for (int k0 = 0; k0 < K; k0 += 8) {
        float4 av = make_float4(0.f,0.f,0.f,0.f);
        float4 bv = make_float4(0.f,0.f,0.f,0.f);
        int am = bm + lrow;
        if (am < M) av = *reinterpret_cast<const float4*>(A + (size_t)am*lda + k0 + lk);
        int wn = bn + lrow;
        if (wn < N) bv = *reinterpret_cast<const float4*>(W + (size_t)wn*ldw + k0 + lk);
        __syncthreads();   // protect previous iteration's reads
        As[lk+0][lrow]=av.x; As[lk+1][lrow]=av.y; As[lk+2][lrow]=av.z; As[lk+3][lrow]=av.w;
        Bs[lk+0][lrow]=bv.x; Bs[lk+1][lrow]=bv.y; Bs[lk+2][lrow]=bv.z; Bs[lk+3][lrow]=bv.w;
        __syncthreads();
#pragma unroll
        for (int k = 0; k < 8; k++) {
            float4 a0 = *reinterpret_cast<const float4*>(&As[k][ty*4]);
            float4 a1 = *reinterpret_cast<const float4*>(&As[k][64 + ty*4]);
            float4 b0 = *reinterpret_cast<const float4*>(&Bs[k][tx*4]);
            float4 b1 = *reinterpret_cast<const float4*>(&Bs[k][64 + tx*4]);
            float ar[8] = {a0.x,a0.y,a0.z,a0.w,a1.x,a1.y,a1.z,a1.w};
            float br[8] = {b0.x,b0.y,b0.z,b0.w,b1.x,b1.y,b1.z,b1.w};
#pragma unroll
            for (int i = 0; i < 8; i++)
#pragma unroll
                for (int j = 0; j < 8; j++) acc[i][j] += ar[i]*br[j];
        }
    }

#pragma unroll
    for (int ri = 0; ri < 2; ri++)
#pragma unroll
    for (int i = 0; i < 4; i++) {
        int m = bm + ri*64 + ty*4 + i;
        if (m >= M) continue;
#pragma unroll
        for (int cj = 0; cj < 2; cj++) {
            int n = bn + cj*64 + tx*4;
            if (n >= N) continue;     // N % 4 == 0 always here, so n..n+3 valid
            float4 o;
            o.x = acc[ri*4+i][cj*4+0] + bias[n+0];
            o.y = acc[ri*4+i][cj*4+1] + bias[n+1];
            o.z = acc[ri*4+i][cj*4+2] + bias[n+2];
            o.w = acc[ri*4+i][cj*4+3] + bias[n+3];
            *reinterpret_cast<float4*>(C + (size_t)m*ldc + n) = o;
        }
    }
}

// ---------------- RMSNorm (strided, optionally in-place) ----------------
__global__ __launch_bounds__(256)
void rmsnorm_kernel(const float* __restrict__ src, float* __restrict__ dst,
                    const float* __restrict__ w, int width, int sstride, int dstride)
{
    int row = blockIdx.x;
    const float* s = src + (size_t)row * sstride;
    float* d = dst + (size_t)row * dstride;

    float ss = 0.f;
    for (int c = threadIdx.x; c < width; c += blockDim.x) { float v = s[c]; ss += v*v; }

    __shared__ float red[8];
#pragma unroll
    for (int off = 16; off; off >>= 1) ss += __shfl_xor_sync(0xffffffffu, ss, off);
    int warp = threadIdx.x >> 5;
    if ((threadIdx.x & 31) == 0) red[warp] = ss;
    __syncthreads();
    if (warp == 0) {
        float v = (threadIdx.x < 8) ? red[threadIdx.x] : 0.f;
#pragma unroll
        for (int off = 4; off; off >>= 1) v += __shfl_xor_sync(0xffffffffu, v, off);
        if (threadIdx.x == 0) red[0] = v;
    }
    __syncthreads();
    float scale = rsqrtf(red[0] / (float)width + 1e-6f);
    for (int c = threadIdx.x; c < width; c += blockDim.x) d[c] = s[c] * scale * w[c];
}

// ---------------- RoPE: q_pe (16 heads) + k_pe (broadcast head), in-place ----------------
__global__ __launch_bounds__(256)
void rope_kernel(float* __restrict__ qb, float* __restrict__ kva)
{
    int row = blockIdx.x;            // 0..4095
    int s = row & (SEQL - 1);        // position within sequence
    for (int p = threadIdx.x; p < 544; p += blockDim.x) {
        int d = p & 31;
        float ang = (float)s * powf(10000.f, -(float)d * (1.f/32.f));
        float sn, c;
        sincosf(ang, &sn, &c);
        float* base;
        if (p < 512) {
            int hh = p >> 5;
            base = qb + (size_t)row*(NHEADS*QKHD) + hh*QKHD + NOPE_D;
        } else {
            base = kva + (size_t)row*(KVLORA+ROPE_D) + KVLORA;
        }
        float x1 = base[d], x2 = base[d+32];
        base[d]    = x1*c - x2*sn;
        base[d+32] = x2*c + x1*sn;
    }
}

// ---------------- Flash attention (fp32, causal, online softmax) ----------------
// q_full: qb[(b,s),h*192 + 0..191] (rope already applied to last 64)
// k_full: nope from kvb[(b,s),h*256 + 0..127], rope from kva[(b,s),512..575] (broadcast)
// v:      kvb[(b,s),h*256 + 128..255]
#define FBR 64
#define FBC 64
#define QKPAD 65

__global__ __launch_bounds__(256)
void flash_kernel(const float* __restrict__ qb,
                  const float* __restrict__ kvb,
                  const float* __restrict__ kva,
                  float* __restrict__ att)
{
    extern __shared__ float sm[];
    float* Qs = sm;                        // [192][65] d-major
    float* Ks = Qs + 192*QKPAD;            // [192][65] d-major
    float* Vs = Ks + 192*QKPAD;            // [64][128]  k-major
    float* Ps = Vs + 64*128;               // [64][65]   k-major (P^T)

    const int qt = blockIdx.x;
    const int h  = blockIdx.y;
    const int b  = blockIdx.z;
    const int s0 = qt * FBR;
    const int tid = threadIdx.x;
    const int tx = tid & 15;               // column lane (cols tx + 16*j)
    const int ty = tid >> 4;               // row group (rows ty*4 + i)

    const float scale = 0.07216878364870323f;   // 1/sqrt(192)

    // load Q tile (prescaled)
    for (int idx = tid; idx < FBR*192; idx += 256) {
        int r = idx / 192, d = idx % 192;
        Qs[d*QKPAD + r] = qb[(size_t)(b*SEQL + s0 + r)*(NHEADS*QKHD) + h*QKHD + d] * scale;
    }

    float m_i[4], l_i[4], O[4][8];
#pragma unroll
    for (int i = 0; i < 4; i++) {
        m_i[i] = -1e30f; l_i[i] = 0.f;
#pragma unroll
        for (int j = 0; j < 8; j++) O[i][j] = 0.f;
    }

    for (int kt = 0; kt <= qt; kt++) {
        __syncthreads();                   // previous PV done (and Q load on iter 0)
        int ks0 = kt * FBC;
        for (int idx = tid; idx < FBC*192; idx += 256) {
            int r = idx / 192, d = idx % 192;
            size_t row = (size_t)(b*SEQL + ks0 + r);
            float v;
            if (d < NOPE_D) v = kvb[row*4096 + h*256 + d];
            else            v = kva[row*576 + KVLORA + (d - NOPE_D)];
            Ks[d*QKPAD + r] = v;
        }
        for (int idx = tid; idx < FBC*128; idx += 256) {
            int r = idx >> 7, d = idx & 127;
            Vs[r*128 + d] = kvb[(size_t)(b*SEQL + ks0 + r)*4096 + h*256 + 128 + d];
        }
        __syncthreads();

        // S = Q K^T
        float s_acc[4][4];
#pragma unroll
        for (int i = 0; i < 4; i++)
#pragma unroll
            for (int j = 0; j < 4; j++) s_acc[i][j] = 0.f;

#pragma unroll 4
        for (int k = 0; k < 192; k++) {
            float a[4], bb[4];
#pragma unroll
            for (int i = 0; i < 4; i++) a[i]  = Qs[k*QKPAD + ty*4 + i];
#pragma unroll
            for (int j = 0; j < 4; j++) bb[j] = Ks[k*QKPAD + tx + 16*j];
#pragma unroll
            for (int i = 0; i < 4; i++)
#pragma unroll
                for (int j = 0; j < 4; j++) s_acc[i][j] += a[i]*bb[j];
        }

        if (kt == qt) {                    // diagonal tile: causal mask
#pragma unroll
            for (int i = 0; i < 4; i++) {
                int rr = ty*4 + i;
#pragma unroll
                for (int j = 0; j < 4; j++)
                    if (tx + 16*j > rr) s_acc[i][j] = -1e30f;
            }
        }

        // online softmax update per row
#pragma unroll
        for (int i = 0; i < 4; i++) {
            float mt = s_acc[i][0];
#pragma unroll
            for (int j = 1; j < 4; j++) mt = fmaxf(mt, s_acc[i][j]);
#pragma unroll
            for (int off = 1; off < 16; off <<= 1)
                mt = fmaxf(mt, __shfl_xor_sync(0xffffffffu, mt, off));
            float mnew = fmaxf(m_i[i], mt);
            float p[4], rs = 0.f;
#pragma unroll
            for (int j = 0; j < 4; j++) { p[j] = expf(s_acc[i][j] - mnew); rs += p[j]; }
#pragma unroll
            for (int off = 1; off < 16; off <<= 1)
                rs += __shfl_xor_sync(0xffffffffu, rs, off);
            float alpha = expf(m_i[i] - mnew);
            m_i[i] = mnew;
            l_i[i] = l_i[i]*alpha + rs;
#pragma unroll
            for (int j = 0; j < 8; j++) O[i][j] *= alpha;
#pragma unroll
            for (int j = 0; j < 4; j++) Ps[(tx + 16*j)*QKPAD + ty*4 + i] = p[j];
        }
        __syncthreads();                   // Ps ready

        // O += P V
#pragma unroll 2
        for (int kc = 0; kc < FBC; kc++) {
            float pr[4], vr[8];
#pragma unroll
            for (int i = 0; i < 4; i++) pr[i] = Ps[kc*QKPAD + ty*4 + i];
#pragma unroll
            for (int j = 0; j < 8; j++) vr[j] = Vs[kc*128 + tx + 16*j];
#pragma unroll
            for (int i = 0; i < 4; i++)
#pragma unroll
                for (int j = 0; j < 8; j++) O[i][j] += pr[i]*vr[j];
        }
    }

    // write normalized output: att[(b,s), h*128 + c]
#pragma unroll
    for (int i = 0; i < 4; i++) {
        float inv = 1.f / l_i[i];
        int row = b*SEQL + s0 + ty*4 + i;
#pragma unroll
        for (int j = 0; j < 8; j++)
            att[(size_t)row*2048 + h*128 + tx + 16*j] = O[i][j] * inv;
    }
}

// ---------------- host launcher ----------------
extern "C" void kernel_launch(void* const* d_in, const int* in_sizes, int n_in,
                              void* d_out, int out_size)
{
    const float* x      = (const float*)d_in[0];
    const float* wqa    = (const float*)d_in[1];
    const float* wqa_b  = (const float*)d_in[2];
    const float* qnw    = (const float*)d_in[3];
    const float* wqb    = (const float*)d_in[4];
    const float* wqb_b  = (const float*)d_in[5];
    const float* wkva   = (const float*)d_in[6];
    const float* wkva_b = (const float*)d_in[7];
    const float* kvnw   = (const float*)d_in[8];
    const float* wkvb   = (const float*)d_in[9];
    const float* wkvb_b = (const float*)d_in[10];
    const float* wo     = (const float*)d_in[11];
    const float* wo_b   = (const float*)d_in[12];
    float* out = (float*)d_out;

    float *qa, *qbp, *kva, *kvb, *att;
    cudaGetSymbolAddress((void**)&qa,  g_qa);
    cudaGetSymbolAddress((void**)&qbp, g_qb);
    cudaGetSymbolAddress((void**)&kva, g_kva);
    cudaGetSymbolAddress((void**)&kvb, g_kvb);
    cudaGetSymbolAddress((void**)&att, g_att);

    const int fl_smem = (2*192*QKPAD + 64*128 + 64*QKPAD) * (int)sizeof(float);
    cudaFuncSetAttribute(flash_kernel, cudaFuncAttributeMaxDynamicSharedMemorySize, fl_smem);

    dim3 t256(256);

    // 1. q_a = x @ wq_a^T + b        (4096 x 1536, K=2048)
    gemm_nt_bias<<<dim3(QLORA/128, ROWS/128), t256>>>(x, DIMX, wqa, DIMX, wqa_b, qa, QLORA, ROWS, QLORA, DIMX);
    // 2. q_a = rmsnorm(q_a)
    rmsnorm_kernel<<<ROWS, t256>>>(qa, qa, qnw, QLORA, QLORA, QLORA);
    // 3. q_b = q_a @ wq_b^T + b      (4096 x 3072, K=1536)
    gemm_nt_bias<<<dim3(3072/128, ROWS/128), t256>>>(qa, QLORA, wqb, QLORA, wqb_b, qbp, 3072, ROWS, 3072, QLORA);
    // 4. kv_a = x @ wkv_a^T + b      (4096 x 576, K=2048)
    gemm_nt_bias<<<dim3((576+127)/128, ROWS/128), t256>>>(x, DIMX, wkva, DIMX, wkva_b, kva, 576, ROWS, 576, DIMX);
    // 5. RoPE on q_pe (q_b) and k_pe (kv_a cols 512..575)
    rope_kernel<<<ROWS, t256>>>(qbp, kva);
    // 6. kv_c = rmsnorm(kv_a[:, :512]) in place (stride 576)
    rmsnorm_kernel<<<ROWS, t256>>>(kva, kva, kvnw, KVLORA, 576, 576);
    // 7. kvb = kv_c @ wkv_b^T + b    (4096 x 4096, K=512; A stride 576)
    gemm_nt_bias<<<dim3(4096/128, ROWS/128), t256>>>(kva, 576, wkvb, KVLORA, wkvb_b, kvb, 4096, ROWS, 4096, KVLORA);
    // 8. causal flash attention -> att (4096 x 2048, layout (b,s,h,128))
    flash_kernel<<<dim3(SEQL/FBR, NHEADS, BSZ), t256, fl_smem>>>(qbp, kvb, kva, att);
    // 9. out = att @ wo^T + b        (4096 x 2048, K=2048)
    gemm_nt_bias<<<dim3(2048/128, ROWS/128), t256>>>(att, 2048, wo, 2048, wo_b, out, 2048, ROWS, 2048, 2048);
}

// round 3
// speedup vs baseline: 1.5343x; 1.5343x over previous
#include <cuda_runtime.h>
#include <cuda_bf16.h>
#include <cstdint>
#include <math.h>

#define SEQL   2048
#define BSZ    2
#define ROWS   (BSZ*SEQL)          // 4096
#define DIMX   2048
#define QLORA  1536
#define KVLORA 512
#define NHEADS 16
#define QKHD   192                 // 128 nope + 64 rope
#define NOPE_D 128
#define ROPE_D 64
#define VHD    128

// ---------------- scratch (static device globals; no allocation) ----------------
__device__ float g_qa [ROWS*QLORA];                 // 4096x1536
__device__ float g_qb [ROWS*(NHEADS*QKHD)];         // 4096x3072
__device__ float g_kva[ROWS*(KVLORA+ROPE_D)];       // 4096x576
__device__ float g_kvb[ROWS*(NHEADS*(NOPE_D+VHD))]; // 4096x4096
__device__ float g_att[ROWS*(NHEADS*VHD)];          // 4096x2048

__device__ __forceinline__ uint32_t smem_to_u32(const void* p) {
    uint32_t a;
    asm("{ .reg .u64 t; cvta.to.shared.u64 t, %1; cvt.u32.u64 %0, t; }" : "=r"(a) : "l"(p));
    return a;
}
#define SWZ(x) ((x) ^ (((x) >> 3) & 0x70))

__device__ __forceinline__ void ldmatrix_x4(uint32_t* r, uint32_t addr) {
    asm volatile("ldmatrix.sync.aligned.m8n8.x4.shared.b16 {%0,%1,%2,%3}, [%4];"
        : "=r"(r[0]), "=r"(r[1]), "=r"(r[2]), "=r"(r[3]) : "r"(addr));
}
__device__ __forceinline__ void mma_bf16(float* c, const uint32_t* a, uint32_t b0, uint32_t b1) {
    asm volatile(
        "mma.sync.aligned.m16n8k16.row.col.f32.bf16.bf16.f32 "
        "{%0,%1,%2,%3}, {%4,%5,%6,%7}, {%8,%9}, {%0,%1,%2,%3};"
        : "+f"(c[0]), "+f"(c[1]), "+f"(c[2]), "+f"(c[3])
        : "r"(a[0]), "r"(a[1]), "r"(a[2]), "r"(a[3]), "r"(b0), "r"(b1));
}

// ============ split-bf16 HMMA GEMM: C[M,N] = A[M,K] @ W[N,K]^T + bias ============
// CTA tile 128x128, K_tile=64, 8 warps (4M x 2N), warp tile 32x64.
// SMEM per stage: Ahi(16K) Alo(16K) Bhi(16K) Blo(16K) = 64K; double buffered.
#define GM_STAGE 65536
#define GM_SMEM  (2*GM_STAGE + 256)

__global__ __launch_bounds__(256, 1)
void gemm_mma(const float* __restrict__ A, int lda,
              const float* __restrict__ W, int ldw,
              const float* __restrict__ bias,
              float* __restrict__ C, int ldc,
              int Nn, int K)
{
    extern __shared__ char smraw[];
    uint32_t sb0 = smem_to_u32(smraw);
    uint32_t sb = (sb0 + 127u) & ~127u;
    char* smp = smraw + (sb - sb0);

    const int tid  = threadIdx.x;
    const int lane = tid & 31;
    const int wid  = tid >> 5;
    const int bm = blockIdx.y * 128;
    const int bn = blockIdx.x * 128;
    const int wm = (wid & 3) * 32;
    const int wn = (wid >> 2) * 64;

    const int lr = tid >> 4;        // 0..127 : row within tile
    const int lk = tid & 15;        // float4 column (4 floats each)

    float acc[2][8][4];
#pragma unroll
    for (int mt = 0; mt < 2; mt++)
#pragma unroll
        for (int nt = 0; nt < 8; nt++)
#pragma unroll
            for (int q = 0; q < 4; q++) acc[mt][nt][q] = 0.f;

    const int nk = K >> 6;
    float4 pa[8], pb[8];

    // ---- prologue: load stage 0 ----
#pragma unroll
    for (int i = 0; i < 8; i++) {
        int r = lr, kq = lk;        // same per-thread coords each iter; rows advance by 16
        r += i * 16;
        pa[i] = *reinterpret_cast<const float4*>(A + (size_t)(bm + r)*lda + kq*4);
        pb[i] = (bn + r < Nn)
              ? *reinterpret_cast<const float4*>(W + (size_t)(bn + r)*ldw + kq*4)
              : make_float4(0.f,0.f,0.f,0.f);
    }
    // STS stage 0
    {
        char* base = smp;
#pragma unroll
        for (int i = 0; i < 8; i++) {
            int r = lr + i*16, kq = lk;
            uint32_t off = SWZ((uint32_t)(r*128 + kq*8));
            // A
            __nv_bfloat162 h01 = __floats2bfloat162_rn(pa[i].x, pa[i].y);
            __nv_bfloat162 h23 = __floats2bfloat162_rn(pa[i].z, pa[i].w);
            __nv_bfloat162 l01 = __floats2bfloat162_rn(pa[i].x - __bfloat162float(h01.x),
                                                       pa[i].y - __bfloat162float(h01.y));
            __nv_bfloat162 l23 = __floats2bfloat162_rn(pa[i].z - __bfloat162float(h23.x),
                                                       pa[i].w - __bfloat162float(h23.y));
            *reinterpret_cast<uint2*>(base + off) =
                make_uint2(*reinterpret_cast<uint32_t*>(&h01), *reinterpret_cast<uint32_t*>(&h23));
            *reinterpret_cast<uint2*>(base + 16384 + off) =
                make_uint2(*reinterpret_cast<uint32_t*>(&l01), *reinterpret_cast<uint32_t*>(&l23));
            // B
            h01 = __floats2bfloat162_rn(pb[i].x, pb[i].y);
            h23 = __floats2bfloat162_rn(pb[i].z, pb[i].w);
            l01 = __floats2bfloat162_rn(pb[i].x - __bfloat162float(h01.x),
                                        pb[i].y - __bfloat162float(h01.y));
            l23 = __floats2bfloat162_rn(pb[i].z - __bfloat162float(h23.x),
                                        pb[i].w - __bfloat162float(h23.y));
            *reinterpret_cast<uint2*>(base + 32768 + off) =
                make_uint2(*reinterpret_cast<uint32_t*>(&h01), *reinterpret_cast<uint32_t*>(&h23));
            *reinterpret_cast<uint2*>(base + 49152 + off) =
                make_uint2(*reinterpret_cast<uint32_t*>(&l01), *reinterpret_cast<uint32_t*>(&l23));
        }
    }
    __syncthreads();

    for (int kt = 0; kt < nk; kt++) {
        const int cur = kt & 1;
        const bool hasNext = (kt + 1) < nk;

        // ---- prefetch LDG for next stage ----
        if (hasNext) {
            int k0 = (kt + 1) << 6;
#pragma unroll
            for (int i = 0; i < 8; i++) {
                int r = lr + i*16, kq = lk;
                pa[i] = *reinterpret_cast<const float4*>(A + (size_t)(bm + r)*lda + k0 + kq*4);
                pb[i] = (bn + r < Nn)
                      ? *reinterpret_cast<const float4*>(W + (size_t)(bn + r)*ldw + k0 + kq*4)
                      : make_float4(0.f,0.f,0.f,0.f);
            }
        }

        // ---- compute current stage ----
        const uint32_t baseA = sb + (uint32_t)cur * GM_STAGE;
        const uint32_t baseB = baseA + 32768;
#pragma unroll
        for (int k16 = 0; k16 < 4; k16++) {
            uint32_t ah[2][4], al[2][4];
#pragma unroll
            for (int mt = 0; mt < 2; mt++) {
                uint32_t row = wm + mt*16 + (lane & 15);
                uint32_t off = SWZ(row*128u + (uint32_t)(k16*32) + ((lane >> 4) << 4));
                ldmatrix_x4(ah[mt], baseA + off);
                ldmatrix_x4(al[mt], baseA + 16384 + off);
            }
            uint32_t bh[16], bl[16];
#pragma unroll
            for (int ng = 0; ng < 4; ng++) {
                uint32_t nrow = wn + ng*16 + ((lane >> 4) << 3) + (lane & 7);
                uint32_t off = SWZ(nrow*128u + (uint32_t)(k16*32) + (((lane >> 3) & 1) << 4));
                ldmatrix_x4(&bh[ng*4], baseB + off);
                ldmatrix_x4(&bl[ng*4], baseB + 16384 + off);
            }
#pragma unroll
            for (int mt = 0; mt < 2; mt++)
#pragma unroll
                for (int nt = 0; nt < 8; nt++) {
                    mma_bf16(acc[mt][nt], ah[mt], bh[nt*2], bh[nt*2+1]);
                    mma_bf16(acc[mt][nt], ah[mt], bl[nt*2], bl[nt*2+1]);
                    mma_bf16(acc[mt][nt], al[mt], bh[nt*2], bh[nt*2+1]);
                }
        }
        __syncthreads();

        // ---- convert + STS next stage ----
        if (hasNext) {
            char* base = smp + (1 - cur) * GM_STAGE;
#pragma unroll
            for (int i = 0; i < 8; i++) {
                int r = lr + i*16, kq = lk;
                uint32_t off = SWZ((uint32_t)(r*128 + kq*8));
                __nv_bfloat162 h01 = __floats2bfloat162_rn(pa[i].x, pa[i].y);
                __nv_bfloat162 h23 = __floats2bfloat162_rn(pa[i].z, pa[i].w);
                __nv_bfloat162 l01 = __floats2bfloat162_rn(pa[i].x - __bfloat162float(h01.x),
                                                           pa[i].y - __bfloat162float(h01.y));
                __nv_bfloat162 l23 = __floats2bfloat162_rn(pa[i].z - __bfloat162float(h23.x),
                                                           pa[i].w - __bfloat162float(h23.y));
                *reinterpret_cast<uint2*>(base + off) =
                    make_uint2(*reinterpret_cast<uint32_t*>(&h01), *reinterpret_cast<uint32_t*>(&h23));
                *reinterpret_cast<uint2*>(base + 16384 + off) =
                    make_uint2(*reinterpret_cast<uint32_t*>(&l01), *reinterpret_cast<uint32_t*>(&l23));
                h01 = __floats2bfloat162_rn(pb[i].x, pb[i].y);
                h23 = __floats2bfloat162_rn(pb[i].z, pb[i].w);
                l01 = __floats2bfloat162_rn(pb[i].x - __bfloat162float(h01.x),
                                            pb[i].y - __bfloat162float(h01.y));
                l23 = __floats2bfloat162_rn(pb[i].z - __bfloat162float(h23.x),
                                            pb[i].w - __bfloat162float(h23.y));
                *reinterpret_cast<uint2*>(base + 32768 + off) =
                    make_uint2(*reinterpret_cast<uint32_t*>(&h01), *reinterpret_cast<uint32_t*>(&h23));
                *reinterpret_cast<uint2*>(base + 49152 + off) =
                    make_uint2(*reinterpret_cast<uint32_t*>(&l01), *reinterpret_cast<uint32_t*>(&l23));
            }
        }
        __syncthreads();
    }

    // ---- epilogue: registers -> GMEM with bias ----
#pragma unroll
    for (int nt = 0; nt < 8; nt++) {
        int col = bn + wn + nt*8 + (lane & 3)*2;
        if (col >= Nn) continue;
        float bx = bias[col], by = bias[col+1];
#pragma unroll
        for (int mt = 0; mt < 2; mt++) {
            int row = bm + wm + mt*16 + (lane >> 2);
            float2 v0 = make_float2(acc[mt][nt][0] + bx, acc[mt][nt][1] + by);
            float2 v1 = make_float2(acc[mt][nt][2] + bx, acc[mt][nt][3] + by);
            *reinterpret_cast<float2*>(C + (size_t)row*ldc + col) = v0;
            *reinterpret_cast<float2*>(C + (size_t)(row+8)*ldc + col) = v1;
        }
    }
}

// ---------------- RMSNorm (strided, optionally in-place) ----------------
__global__ __launch_bounds__(256)
void rmsnorm_kernel(const float* __restrict__ src, float* __restrict__ dst,
                    const float* __restrict__ w, int width, int sstride, int dstride)
{
    int row = blockIdx.x;
    const float* s = src + (size_t)row * sstride;
    float* d = dst + (size_t)row * dstride;

    float ss = 0.f;
    for (int c = threadIdx.x; c < width; c += blockDim.x) { float v = s[c]; ss += v*v; }

    __shared__ float red[8];
#pragma unroll
    for (int off = 16; off; off >>= 1) ss += __shfl_xor_sync(0xffffffffu, ss, off);
    int warp = threadIdx.x >> 5;
    if ((threadIdx.x & 31) == 0) red[warp] = ss;
    __syncthreads();
    if (warp == 0) {
        float v = (threadIdx.x < 8) ? red[threadIdx.x] : 0.f;
#pragma unroll
        for (int off = 4; off; off >>= 1) v += __shfl_xor_sync(0xffffffffu, v, off);
        if (threadIdx.x == 0) red[0] = v;
    }
    __syncthreads();
    float scale = rsqrtf(red[0] / (float)width + 1e-6f);
    for (int c = threadIdx.x; c < width; c += blockDim.x) d[c] = s[c] * scale * w[c];
}

// ---------------- RoPE: q_pe (16 heads) + k_pe (broadcast head), in-place ----------------
__global__ __launch_bounds__(256)
void rope_kernel(float* __restrict__ qb, float* __restrict__ kva)
{
    int row = blockIdx.x;            // 0..4095
    int s = row & (SEQL - 1);        // position within sequence
    for (int p = threadIdx.x; p < 544; p += blockDim.x) {
        int d = p & 31;
        float ang = (float)s * powf(10000.f, -(float)d * (1.f/32.f));
        float sn, c;
        sincosf(ang, &sn, &c);
        float* base;
        if (p < 512) {
            int hh = p >> 5;
            base = qb + (size_t)row*(NHEADS*QKHD) + hh*QKHD + NOPE_D;
        } else {
            base = kva + (size_t)row*(KVLORA+ROPE_D) + KVLORA;
        }
        float x1 = base[d], x2 = base[d+32];
        base[d]    = x1*c - x2*sn;
        base[d+32] = x2*c + x1*sn;
    }
}

// ---------------- Flash attention (fp32, causal, online softmax) ----------------
#define FBR 64
#define FBC 64
#define QKPAD 65

__global__ __launch_bounds__(256)
void flash_kernel(const float* __restrict__ qb,
                  const float* __restrict__ kvb,
                  const float* __restrict__ kva,
                  float* __restrict__ att)
{
    extern __shared__ float smf[];
    float* Qs = smf;                       // [192][65] d-major
    float* Ks = Qs + 192*QKPAD;            // [192][65] d-major
    float* Vs = Ks + 192*QKPAD;            // [64][128]  k-major
    float* Ps = Vs + 64*128;               // [64][65]   k-major (P^T)

    const int qt = blockIdx.x;
    const int h  = blockIdx.y;
    const int b  = blockIdx.z;
    const int s0 = qt * FBR;
    const int tid = threadIdx.x;
    const int tx = tid & 15;               // column lane (cols tx + 16*j)
    const int ty = tid >> 4;               // row group (rows ty*4 + i)

    const float scale = 0.07216878364870323f;   // 1/sqrt(192)

    for (int idx = tid; idx < FBR*192; idx += 256) {
        int r = idx / 192, d = idx % 192;
        Qs[d*QKPAD + r] = qb[(size_t)(b*SEQL + s0 + r)*(NHEADS*QKHD) + h*QKHD + d] * scale;
    }

    float m_i[4], l_i[4], O[4][8];
#pragma unroll
    for (int i = 0; i < 4; i++) {
        m_i[i] = -1e30f; l_i[i] = 0.f;
#pragma unroll
        for (int j = 0; j < 8; j++) O[i][j] = 0.f;
    }

    for (int kt = 0; kt <= qt; kt++) {
        __syncthreads();
        int ks0 = kt * FBC;
        for (int idx = tid; idx < FBC*192; idx += 256) {
            int r = idx / 192, d = idx % 192;
            size_t row = (size_t)(b*SEQL + ks0 + r);
            float v;
            if (d < NOPE_D) v = kvb[row*4096 + h*256 + d];
            else            v = kva[row*576 + KVLORA + (d - NOPE_D)];
            Ks[d*QKPAD + r] = v;
        }
        for (int idx = tid; idx < FBC*128; idx += 256) {
            int r = idx >> 7, d = idx & 127;
            Vs[r*128 + d] = kvb[(size_t)(b*SEQL + ks0 + r)*4096 + h*256 + 128 + d];
        }
        __syncthreads();

        float s_acc[4][4];
#pragma unroll
        for (int i = 0; i < 4; i++)
#pragma unroll
            for (int j = 0; j < 4; j++) s_acc[i][j] = 0.f;

#pragma unroll 4
        for (int k = 0; k < 192; k++) {
            float a[4], bb[4];
#pragma unroll
            for (int i = 0; i < 4; i++) a[i]  = Qs[k*QKPAD + ty*4 + i];
#pragma unroll
            for (int j = 0; j < 4; j++) bb[j] = Ks[k*QKPAD + tx + 16*j];
#pragma unroll
            for (int i = 0; i < 4; i++)
#pragma unroll
                for (int j = 0; j < 4; j++) s_acc[i][j] += a[i]*bb[j];
        }

        if (kt == qt) {
#pragma unroll
            for (int i = 0; i < 4; i++) {
                int rr = ty*4 + i;
#pragma unroll
                for (int j = 0; j < 4; j++)
                    if (tx + 16*j > rr) s_acc[i][j] = -1e30f;
            }
        }

#pragma unroll
        for (int i = 0; i < 4; i++) {
            float mt = s_acc[i][0];
#pragma unroll
            for (int j = 1; j < 4; j++) mt = fmaxf(mt, s_acc[i][j]);
#pragma unroll
            for (int off = 1; off < 16; off <<= 1)
                mt = fmaxf(mt, __shfl_xor_sync(0xffffffffu, mt, off));
            float mnew = fmaxf(m_i[i], mt);
            float p[4], rs = 0.f;
#pragma unroll
            for (int j = 0; j < 4; j++) { p[j] = expf(s_acc[i][j] - mnew); rs += p[j]; }
#pragma unroll
            for (int off = 1; off < 16; off <<= 1)
                rs += __shfl_xor_sync(0xffffffffu, rs, off);
            float alpha = expf(m_i[i] - mnew);
            m_i[i] = mnew;
            l_i[i] = l_i[i]*alpha + rs;
#pragma unroll
            for (int j = 0; j < 8; j++) O[i][j] *= alpha;
#pragma unroll
            for (int j = 0; j < 4; j++) Ps[(tx + 16*j)*QKPAD + ty*4 + i] = p[j];
        }
        __syncthreads();

#pragma unroll 2
        for (int kc = 0; kc < FBC; kc++) {
            float pr[4], vr[8];
#pragma unroll
            for (int i = 0; i < 4; i++) pr[i] = Ps[kc*QKPAD + ty*4 + i];
#pragma unroll
            for (int j = 0; j < 8; j++) vr[j] = Vs[kc*128 + tx + 16*j];
#pragma unroll
            for (int i = 0; i < 4; i++)
#pragma unroll
                for (int j = 0; j < 8; j++) O[i][j] += pr[i]*vr[j];
        }
    }

#pragma unroll
    for (int i = 0; i < 4; i++) {
        float inv = 1.f / l_i[i];
        int row = b*SEQL + s0 + ty*4 + i;
#pragma unroll
        for (int j = 0; j < 8; j++)
            att[(size_t)row*2048 + h*128 + tx + 16*j] = O[i][j] * inv;
    }
}

// ---------------- host launcher ----------------
extern "C" void kernel_launch(void* const* d_in, const int* in_sizes, int n_in,
                              void* d_out, int out_size)
{
    const float* x      = (const float*)d_in[0];
    const float* wqa    = (const float*)d_in[1];
    const float* wqa_b  = (const float*)d_in[2];
    const float* qnw    = (const float*)d_in[3];
    const float* wqb    = (const float*)d_in[4];
    const float* wqb_b  = (const float*)d_in[5];
    const float* wkva   = (const float*)d_in[6];
    const float* wkva_b = (const float*)d_in[7];
    const float* kvnw   = (const float*)d_in[8];
    const float* wkvb   = (const float*)d_in[9];
    const float* wkvb_b = (const float*)d_in[10];
    const float* wo     = (const float*)d_in[11];
    const float* wo_b   = (const float*)d_in[12];
    float* out = (float*)d_out;

    float *qa, *qbp, *kva, *kvb, *att;
    cudaGetSymbolAddress((void**)&qa,  g_qa);
    cudaGetSymbolAddress((void**)&qbp, g_qb);
    cudaGetSymbolAddress((void**)&kva, g_kva);
    cudaGetSymbolAddress((void**)&kvb, g_kvb);
    cudaGetSymbolAddress((void**)&att, g_att);

    const int fl_smem = (2*192*QKPAD + 64*128 + 64*QKPAD) * (int)sizeof(float);
    cudaFuncSetAttribute(flash_kernel, cudaFuncAttributeMaxDynamicSharedMemorySize, fl_smem);
    cudaFuncSetAttribute(gemm_mma, cudaFuncAttributeMaxDynamicSharedMemorySize, GM_SMEM);

    dim3 t256(256);

    // 1. q_a = x @ wq_a^T + b        (4096 x 1536, K=2048)
    gemm_mma<<<dim3(QLORA/128, ROWS/128), t256, GM_SMEM>>>(x, DIMX, wqa, DIMX, wqa_b, qa, QLORA, QLORA, DIMX);
    // 2. q_a = rmsnorm(q_a)
    rmsnorm_kernel<<<ROWS, t256>>>(qa, qa, qnw, QLORA, QLORA, QLORA);
    // 3. q_b = q_a @ wq_b^T + b      (4096 x 3072, K=1536)
    gemm_mma<<<dim3(3072/128, ROWS/128), t256, GM_SMEM>>>(qa, QLORA, wqb, QLORA, wqb_b, qbp, 3072, 3072, QLORA);
    // 4. kv_a = x @ wkv_a^T + b      (4096 x 576, K=2048)
    gemm_mma<<<dim3((576+127)/128, ROWS/128), t256, GM_SMEM>>>(x, DIMX, wkva, DIMX, wkva_b, kva, 576, 576, DIMX);
    // 5. RoPE on q_pe (q_b) and k_pe (kv_a cols 512..575)
    rope_kernel<<<ROWS, t256>>>(qbp, kva);
    // 6. kv_c = rmsnorm(kv_a[:, :512]) in place (stride 576)
    rmsnorm_kernel<<<ROWS, t256>>>(kva, kva, kvnw, KVLORA, 576, 576);
    // 7. kvb = kv_c @ wkv_b^T + b    (4096 x 4096, K=512; A stride 576)
    gemm_mma<<<dim3(4096/128, ROWS/128), t256, GM_SMEM>>>(kva, 576, wkvb, KVLORA, wkvb_b, kvb, 4096, 4096, KVLORA);
    // 8. causal flash attention -> att (4096 x 2048, layout (b,s,h,128))
    flash_kernel<<<dim3(SEQL/FBR, NHEADS, BSZ), t256, fl_smem>>>(qbp, kvb, kva, att);
    // 9. out = att @ wo^T + b        (4096 x 2048, K=2048)
    gemm_mma<<<dim3(2048/128, ROWS/128), t256, GM_SMEM>>>(att, 2048, wo, 2048, wo_b, out, 2048, 2048, DIMX);
}

// round 4
// speedup vs baseline: 3.6840x; 2.4011x over previous
#include <cuda_runtime.h>
#include <cuda_bf16.h>
#include <cstdint>
#include <math.h>

#define SEQL   2048
#define BSZ    2
#define ROWS   (BSZ*SEQL)          // 4096
#define DIMX   2048
#define QLORA  1536
#define KVLORA 512
#define NHEADS 16
#define QKHD   192                 // 128 nope + 64 rope
#define NOPE_D 128
#define ROPE_D 64
#define VHD    128

// ---------------- scratch (static device globals; no allocation) ----------------
__device__ float g_qa [ROWS*QLORA];                 // 4096x1536
__device__ float g_qb [ROWS*(NHEADS*QKHD)];         // 4096x3072
__device__ float g_kva[ROWS*(KVLORA+ROPE_D)];       // 4096x576
__device__ float g_kvb[ROWS*(NHEADS*(NOPE_D+VHD))]; // 4096x4096
__device__ float g_att[ROWS*(NHEADS*VHD)];          // 4096x2048

__device__ __forceinline__ uint32_t smem_to_u32(const void* p) {
    uint32_t a;
    asm("{ .reg .u64 t; cvta.to.shared.u64 t, %1; cvt.u32.u64 %0, t; }" : "=r"(a) : "l"(p));
    return a;
}
#define SWZ(x) ((x) ^ (((x) >> 3) & 0x70))

__device__ __forceinline__ void ldmatrix_x4(uint32_t* r, uint32_t addr) {
    asm volatile("ldmatrix.sync.aligned.m8n8.x4.shared.b16 {%0,%1,%2,%3}, [%4];"
        : "=r"(r[0]), "=r"(r[1]), "=r"(r[2]), "=r"(r[3]) : "r"(addr));
}
__device__ __forceinline__ void ldmatrix_x4_trans(uint32_t* r, uint32_t addr) {
    asm volatile("ldmatrix.sync.aligned.m8n8.x4.trans.shared.b16 {%0,%1,%2,%3}, [%4];"
        : "=r"(r[0]), "=r"(r[1]), "=r"(r[2]), "=r"(r[3]) : "r"(addr));
}
__device__ __forceinline__ void mma_bf16(float* c, const uint32_t* a, uint32_t b0, uint32_t b1) {
    asm volatile(
        "mma.sync.aligned.m16n8k16.row.col.f32.bf16.bf16.f32 "
        "{%0,%1,%2,%3}, {%4,%5,%6,%7}, {%8,%9}, {%0,%1,%2,%3};"
        : "+f"(c[0]), "+f"(c[1]), "+f"(c[2]), "+f"(c[3])
        : "r"(a[0]), "r"(a[1]), "r"(a[2]), "r"(a[3]), "r"(b0), "r"(b1));
}
__device__ __forceinline__ uint32_t pack_bf16x2(float lo, float hi) {
    __nv_bfloat162 h = __floats2bfloat162_rn(lo, hi);
    return *reinterpret_cast<uint32_t*>(&h);
}

// ============ split-bf16 HMMA GEMM: C[M,N] = A[M,K] @ W[N,K]^T + bias ============
#define GM_STAGE 65536
#define GM_SMEM  (2*GM_STAGE + 256)

__global__ __launch_bounds__(256, 1)
void gemm_mma(const float* __restrict__ A, int lda,
              const float* __restrict__ W, int ldw,
              const float* __restrict__ bias,
              float* __restrict__ C, int ldc,
              int Nn, int K)
{
    extern __shared__ char smraw[];
    uint32_t sb0 = smem_to_u32(smraw);
    uint32_t sb = (sb0 + 127u) & ~127u;
    char* smp = smraw + (sb - sb0);

    const int tid  = threadIdx.x;
    const int lane = tid & 31;
    const int wid  = tid >> 5;
    const int bm = blockIdx.y * 128;
    const int bn = blockIdx.x * 128;
    const int wm = (wid & 3) * 32;
    const int wn = (wid >> 2) * 64;

    const int lr = tid >> 4;
    const int lk = tid & 15;

    float acc[2][8][4];
#pragma unroll
    for (int mt = 0; mt < 2; mt++)
#pragma unroll
        for (int nt = 0; nt < 8; nt++)
#pragma unroll
            for (int q = 0; q < 4; q++) acc[mt][nt][q] = 0.f;

    const int nk = K >> 6;
    float4 pa[8], pb[8];

#pragma unroll
    for (int i = 0; i < 8; i++) {
        int r = lr + i * 16;
        pa[i] = *reinterpret_cast<const float4*>(A + (size_t)(bm + r)*lda + lk*4);
        pb[i] = (bn + r < Nn)
              ? *reinterpret_cast<const float4*>(W + (size_t)(bn + r)*ldw + lk*4)
              : make_float4(0.f,0.f,0.f,0.f);
    }
    {
        char* base = smp;
#pragma unroll
        for (int i = 0; i < 8; i++) {
            int r = lr + i*16;
            uint32_t off = SWZ((uint32_t)(r*128 + lk*8));
            __nv_bfloat162 h01 = __floats2bfloat162_rn(pa[i].x, pa[i].y);
            __nv_bfloat162 h23 = __floats2bfloat162_rn(pa[i].z, pa[i].w);
            __nv_bfloat162 l01 = __floats2bfloat162_rn(pa[i].x - __bfloat162float(h01.x),
                                                       pa[i].y - __bfloat162float(h01.y));
            __nv_bfloat162 l23 = __floats2bfloat162_rn(pa[i].z - __bfloat162float(h23.x),
                                                       pa[i].w - __bfloat162float(h23.y));
            *reinterpret_cast<uint2*>(base + off) =
                make_uint2(*reinterpret_cast<uint32_t*>(&h01), *reinterpret_cast<uint32_t*>(&h23));
            *reinterpret_cast<uint2*>(base + 16384 + off) =
                make_uint2(*reinterpret_cast<uint32_t*>(&l01), *reinterpret_cast<uint32_t*>(&l23));
            h01 = __floats2bfloat162_rn(pb[i].x, pb[i].y);
            h23 = __floats2bfloat162_rn(pb[i].z, pb[i].w);
            l01 = __floats2bfloat162_rn(pb[i].x - __bfloat162float(h01.x),
                                        pb[i].y - __bfloat162float(h01.y));
            l23 = __floats2bfloat162_rn(pb[i].z - __bfloat162float(h23.x),
                                        pb[i].w - __bfloat162float(h23.y));
            *reinterpret_cast<uint2*>(base + 32768 + off) =
                make_uint2(*reinterpret_cast<uint32_t*>(&h01), *reinterpret_cast<uint32_t*>(&h23));
            *reinterpret_cast<uint2*>(base + 49152 + off) =
                make_uint2(*reinterpret_cast<uint32_t*>(&l01), *reinterpret_cast<uint32_t*>(&l23));
        }
    }
    __syncthreads();

    for (int kt = 0; kt < nk; kt++) {
        const int cur = kt & 1;
        const bool hasNext = (kt + 1) < nk;

        if (hasNext) {
            int k0 = (kt + 1) << 6;
#pragma unroll
            for (int i = 0; i < 8; i++) {
                int r = lr + i*16;
                pa[i] = *reinterpret_cast<const float4*>(A + (size_t)(bm + r)*lda + k0 + lk*4);
                pb[i] = (bn + r < Nn)
                      ? *reinterpret_cast<const float4*>(W + (size_t)(bn + r)*ldw + k0 + lk*4)
                      : make_float4(0.f,0.f,0.f,0.f);
            }
        }

        const uint32_t baseA = sb + (uint32_t)cur * GM_STAGE;
        const uint32_t baseB = baseA + 32768;
#pragma unroll
        for (int k16 = 0; k16 < 4; k16++) {
            uint32_t ah[2][4], al[2][4];
#pragma unroll
            for (int mt = 0; mt < 2; mt++) {
                uint32_t row = wm + mt*16 + (lane & 15);
                uint32_t off = SWZ(row*128u + (uint32_t)(k16*32) + ((lane >> 4) << 4));
                ldmatrix_x4(ah[mt], baseA + off);
                ldmatrix_x4(al[mt], baseA + 16384 + off);
            }
            uint32_t bh[16], bl[16];
#pragma unroll
            for (int ng = 0; ng < 4; ng++) {
                uint32_t nrow = wn + ng*16 + ((lane >> 4) << 3) + (lane & 7);
                uint32_t off = SWZ(nrow*128u + (uint32_t)(k16*32) + (((lane >> 3) & 1) << 4));
                ldmatrix_x4(&bh[ng*4], baseB + off);
                ldmatrix_x4(&bl[ng*4], baseB + 16384 + off);
            }
#pragma unroll
            for (int mt = 0; mt < 2; mt++)
#pragma unroll
                for (int nt = 0; nt < 8; nt++) {
                    mma_bf16(acc[mt][nt], ah[mt], bh[nt*2], bh[nt*2+1]);
                    mma_bf16(acc[mt][nt], ah[mt], bl[nt*2], bl[nt*2+1]);
                    mma_bf16(acc[mt][nt], al[mt], bh[nt*2], bh[nt*2+1]);
                }
        }
        __syncthreads();

        if (hasNext) {
            char* base = smp + (1 - cur) * GM_STAGE;
#pragma unroll
            for (int i = 0; i < 8; i++) {
                int r = lr + i*16;
                uint32_t off = SWZ((uint32_t)(r*128 + lk*8));
                __nv_bfloat162 h01 = __floats2bfloat162_rn(pa[i].x, pa[i].y);
                __nv_bfloat162 h23 = __floats2bfloat162_rn(pa[i].z, pa[i].w);
                __nv_bfloat162 l01 = __floats2bfloat162_rn(pa[i].x - __bfloat162float(h01.x),
                                                           pa[i].y - __bfloat162float(h01.y));
                __nv_bfloat162 l23 = __floats2bfloat162_rn(pa[i].z - __bfloat162float(h23.x),
                                                           pa[i].w - __bfloat162float(h23.y));
                *reinterpret_cast<uint2*>(base + off) =
                    make_uint2(*reinterpret_cast<uint32_t*>(&h01), *reinterpret_cast<uint32_t*>(&h23));
                *reinterpret_cast<uint2*>(base + 16384 + off) =
                    make_uint2(*reinterpret_cast<uint32_t*>(&l01), *reinterpret_cast<uint32_t*>(&l23));
                h01 = __floats2bfloat162_rn(pb[i].x, pb[i].y);
                h23 = __floats2bfloat162_rn(pb[i].z, pb[i].w);
                l01 = __floats2bfloat162_rn(pb[i].x - __bfloat162float(h01.x),
                                            pb[i].y - __bfloat162float(h01.y));
                l23 = __floats2bfloat162_rn(pb[i].z - __bfloat162float(h23.x),
                                            pb[i].w - __bfloat162float(h23.y));
                *reinterpret_cast<uint2*>(base + 32768 + off) =
                    make_uint2(*reinterpret_cast<uint32_t*>(&h01), *reinterpret_cast<uint32_t*>(&h23));
                *reinterpret_cast<uint2*>(base + 49152 + off) =
                    make_uint2(*reinterpret_cast<uint32_t*>(&l01), *reinterpret_cast<uint32_t*>(&l23));
            }
        }
        __syncthreads();
    }

#pragma unroll
    for (int nt = 0; nt < 8; nt++) {
        int col = bn + wn + nt*8 + (lane & 3)*2;
        if (col >= Nn) continue;
        float bx = bias[col], by = bias[col+1];
#pragma unroll
        for (int mt = 0; mt < 2; mt++) {
            int row = bm + wm + mt*16 + (lane >> 2);
            float2 v0 = make_float2(acc[mt][nt][0] + bx, acc[mt][nt][1] + by);
            float2 v1 = make_float2(acc[mt][nt][2] + bx, acc[mt][nt][3] + by);
            *reinterpret_cast<float2*>(C + (size_t)row*ldc + col) = v0;
            *reinterpret_cast<float2*>(C + (size_t)(row+8)*ldc + col) = v1;
        }
    }
}

// ---------------- RMSNorm ----------------
__global__ __launch_bounds__(256)
void rmsnorm_kernel(const float* __restrict__ src, float* __restrict__ dst,
                    const float* __restrict__ w, int width, int sstride, int dstride)
{
    int row = blockIdx.x;
    const float* s = src + (size_t)row * sstride;
    float* d = dst + (size_t)row * dstride;

    float ss = 0.f;
    for (int c = threadIdx.x; c < width; c += blockDim.x) { float v = s[c]; ss += v*v; }

    __shared__ float red[8];
#pragma unroll
    for (int off = 16; off; off >>= 1) ss += __shfl_xor_sync(0xffffffffu, ss, off);
    int warp = threadIdx.x >> 5;
    if ((threadIdx.x & 31) == 0) red[warp] = ss;
    __syncthreads();
    if (warp == 0) {
        float v = (threadIdx.x < 8) ? red[threadIdx.x] : 0.f;
#pragma unroll
        for (int off = 4; off; off >>= 1) v += __shfl_xor_sync(0xffffffffu, v, off);
        if (threadIdx.x == 0) red[0] = v;
    }
    __syncthreads();
    float scale = rsqrtf(red[0] / (float)width + 1e-6f);
    for (int c = threadIdx.x; c < width; c += blockDim.x) d[c] = s[c] * scale * w[c];
}

// ---------------- RoPE ----------------
__global__ __launch_bounds__(256)
void rope_kernel(float* __restrict__ qb, float* __restrict__ kva)
{
    int row = blockIdx.x;
    int s = row & (SEQL - 1);
    for (int p = threadIdx.x; p < 544; p += blockDim.x) {
        int d = p & 31;
        float ang = (float)s * powf(10000.f, -(float)d * (1.f/32.f));
        float sn, c;
        sincosf(ang, &sn, &c);
        float* base;
        if (p < 512) {
            int hh = p >> 5;
            base = qb + (size_t)row*(NHEADS*QKHD) + hh*QKHD + NOPE_D;
        } else {
            base = kva + (size_t)row*(KVLORA+ROPE_D) + KVLORA;
        }
        float x1 = base[d], x2 = base[d+32];
        base[d]    = x1*c - x2*sn;
        base[d+32] = x2*c + x1*sn;
    }
}

// ============ Flash attention via mma.sync (split-bf16) ============
// Br=128 rows/block, Bc=64, 8 warps, each warp 16 rows x full 64 cols.
// SMEM: Qh/Ql (3 chunks of 128x64), Kh/Kl (3 chunks 64x64), Vh/Vl (2 chunks 64x64)
#define FL_QH 0
#define FL_QL 49152
#define FL_KH 98304
#define FL_KL 122880
#define FL_VH 147456
#define FL_VL 163840
#define FL_SMEM 180224

__global__ __launch_bounds__(256, 1)
void flash_mma(const float* __restrict__ qb,
               const float* __restrict__ kvb,
               const float* __restrict__ kva,
               float* __restrict__ att)
{
    extern __shared__ char smraw[];
    uint32_t sb0 = smem_to_u32(smraw);
    uint32_t sb = (sb0 + 127u) & ~127u;
    char* smp = smraw + (sb - sb0);

    const int qt = blockIdx.x;
    const int h  = blockIdx.y;
    const int b  = blockIdx.z;
    const int s0 = qt * 128;
    const int bb = b * SEQL;
    const int tid  = threadIdx.x;
    const int lane = tid & 31;
    const int wid  = tid >> 5;
    const int wrow = wid * 16;          // warp's row base within block
    const float scale = 0.07216878364870323f;  // 1/sqrt(192)

    // ---- load Q (128 x 192), prescaled, hi/lo ----
#pragma unroll
    for (int i = 0; i < 24; i++) {
        int idx = tid + i*256;          // 6144 float4
        int row = idx / 48;
        int d = (idx - row*48) * 4;
        float4 v = *reinterpret_cast<const float4*>(
            qb + (size_t)(bb + s0 + row)*3072 + h*192 + d);
        v.x *= scale; v.y *= scale; v.z *= scale; v.w *= scale;
        int ch = d >> 6, dc = d & 63;
        uint32_t off = SWZ((uint32_t)(row*128 + dc*2));
        __nv_bfloat162 h01 = __floats2bfloat162_rn(v.x, v.y);
        __nv_bfloat162 h23 = __floats2bfloat162_rn(v.z, v.w);
        __nv_bfloat162 l01 = __floats2bfloat162_rn(v.x - __bfloat162float(h01.x),
                                                   v.y - __bfloat162float(h01.y));
        __nv_bfloat162 l23 = __floats2bfloat162_rn(v.z - __bfloat162float(h23.x),
                                                   v.w - __bfloat162float(h23.y));
        *reinterpret_cast<uint2*>(smp + FL_QH + ch*16384 + off) =
            make_uint2(*reinterpret_cast<uint32_t*>(&h01), *reinterpret_cast<uint32_t*>(&h23));
        *reinterpret_cast<uint2*>(smp + FL_QL + ch*16384 + off) =
            make_uint2(*reinterpret_cast<uint32_t*>(&l01), *reinterpret_cast<uint32_t*>(&l23));
    }

    float oc[16][4];
#pragma unroll
    for (int nt = 0; nt < 16; nt++)
#pragma unroll
        for (int q = 0; q < 4; q++) oc[nt][q] = 0.f;
    float m0 = -1e30f, m1 = -1e30f, l0 = 0.f, l1 = 0.f;

    const int rg0 = s0 + wrow + (lane >> 2);
    const int rg1 = rg0 + 8;
    const int nkt = 2*qt + 2;

    for (int kt = 0; kt < nkt; kt++) {
        if (kt > 0) __syncthreads();
        const int ks0 = kt * 64;

        // ---- load K (64 x 192) hi/lo ----
#pragma unroll
        for (int i = 0; i < 8; i++) {
            int idx = tid + i*256;      // 2048
            int row = idx >> 5;
            int d = (idx & 31) * 4;
            float4 v = *reinterpret_cast<const float4*>(
                kvb + (size_t)(bb + ks0 + row)*4096 + h*256 + d);
            int ch = d >> 6, dc = d & 63;
            uint32_t off = SWZ((uint32_t)(row*128 + dc*2));
            __nv_bfloat162 h01 = __floats2bfloat162_rn(v.x, v.y);
            __nv_bfloat162 h23 = __floats2bfloat162_rn(v.z, v.w);
            __nv_bfloat162 l01 = __floats2bfloat162_rn(v.x - __bfloat162float(h01.x),
                                                       v.y - __bfloat162float(h01.y));
            __nv_bfloat162 l23 = __floats2bfloat162_rn(v.z - __bfloat162float(h23.x),
                                                       v.w - __bfloat162float(h23.y));
            *reinterpret_cast<uint2*>(smp + FL_KH + ch*8192 + off) =
                make_uint2(*reinterpret_cast<uint32_t*>(&h01), *reinterpret_cast<uint32_t*>(&h23));
            *reinterpret_cast<uint2*>(smp + FL_KL + ch*8192 + off) =
                make_uint2(*reinterpret_cast<uint32_t*>(&l01), *reinterpret_cast<uint32_t*>(&l23));
        }
        // rope chunk (chunk 2) from kva
#pragma unroll
        for (int i = 0; i < 4; i++) {
            int idx = tid + i*256;      // 1024
            int row = idx >> 4;
            int d2 = (idx & 15) * 4;
            float4 v = *reinterpret_cast<const float4*>(
                kva + (size_t)(bb + ks0 + row)*576 + 512 + d2);
            uint32_t off = SWZ((uint32_t)(row*128 + d2*2));
            __nv_bfloat162 h01 = __floats2bfloat162_rn(v.x, v.y);
            __nv_bfloat162 h23 = __floats2bfloat162_rn(v.z, v.w);
            __nv_bfloat162 l01 = __floats2bfloat162_rn(v.x - __bfloat162float(h01.x),
                                                       v.y - __bfloat162float(h01.y));
            __nv_bfloat162 l23 = __floats2bfloat162_rn(v.z - __bfloat162float(h23.x),
                                                       v.w - __bfloat162float(h23.y));
            *reinterpret_cast<uint2*>(smp + FL_KH + 2*8192 + off) =
                make_uint2(*reinterpret_cast<uint32_t*>(&h01), *reinterpret_cast<uint32_t*>(&h23));
            *reinterpret_cast<uint2*>(smp + FL_KL + 2*8192 + off) =
                make_uint2(*reinterpret_cast<uint32_t*>(&l01), *reinterpret_cast<uint32_t*>(&l23));
        }
        // ---- load V (64 x 128) hi/lo, row-major ----
#pragma unroll
        for (int i = 0; i < 8; i++) {
            int idx = tid + i*256;
            int row = idx >> 5;
            int d = (idx & 31) * 4;
            float4 v = *reinterpret_cast<const float4*>(
                kvb + (size_t)(bb + ks0 + row)*4096 + h*256 + 128 + d);
            int ch = d >> 6, dc = d & 63;
            uint32_t off = SWZ((uint32_t)(row*128 + dc*2));
            __nv_bfloat162 h01 = __floats2bfloat162_rn(v.x, v.y);
            __nv_bfloat162 h23 = __floats2bfloat162_rn(v.z, v.w);
            __nv_bfloat162 l01 = __floats2bfloat162_rn(v.x - __bfloat162float(h01.x),
                                                       v.y - __bfloat162float(h01.y));
            __nv_bfloat162 l23 = __floats2bfloat162_rn(v.z - __bfloat162float(h23.x),
                                                       v.w - __bfloat162float(h23.y));
            *reinterpret_cast<uint2*>(smp + FL_VH + ch*8192 + off) =
                make_uint2(*reinterpret_cast<uint32_t*>(&h01), *reinterpret_cast<uint32_t*>(&h23));
            *reinterpret_cast<uint2*>(smp + FL_VL + ch*8192 + off) =
                make_uint2(*reinterpret_cast<uint32_t*>(&l01), *reinterpret_cast<uint32_t*>(&l23));
        }
        __syncthreads();

        // fully-masked tile for this warp? (ks0 multiple of 16 => ks0 <= wrow base)
        if (ks0 > s0 + wrow + 15) continue;

        // ---- S = Q K^T (split-bf16, 3 products) ----
        float sc[8][4];
#pragma unroll
        for (int nt = 0; nt < 8; nt++)
#pragma unroll
            for (int q = 0; q < 4; q++) sc[nt][q] = 0.f;

#pragma unroll
        for (int ks = 0; ks < 12; ks++) {
            int ch = ks >> 2;
            uint32_t kb = (uint32_t)((ks & 3) * 32);
            uint32_t ah[4], al[4];
            {
                uint32_t row = wrow + (lane & 15);
                uint32_t off = SWZ(row*128u + kb + ((lane >> 4) << 4));
                ldmatrix_x4(ah, sb + FL_QH + ch*16384 + off);
                ldmatrix_x4(al, sb + FL_QL + ch*16384 + off);
            }
            uint32_t bh[16], bl[16];
#pragma unroll
            for (int ng = 0; ng < 4; ng++) {
                uint32_t nrow = ng*16 + ((lane >> 4) << 3) + (lane & 7);
                uint32_t off = SWZ(nrow*128u + kb + (((lane >> 3) & 1) << 4));
                ldmatrix_x4(&bh[ng*4], sb + FL_KH + ch*8192 + off);
                ldmatrix_x4(&bl[ng*4], sb + FL_KL + ch*8192 + off);
            }
#pragma unroll
            for (int nt = 0; nt < 8; nt++) {
                mma_bf16(sc[nt], ah, bh[nt*2], bh[nt*2+1]);
                mma_bf16(sc[nt], ah, bl[nt*2], bl[nt*2+1]);
                mma_bf16(sc[nt], al, bh[nt*2], bh[nt*2+1]);
            }
        }

        // ---- causal mask ----
        if (ks0 + 63 > s0 + wrow) {
#pragma unroll
            for (int nt = 0; nt < 8; nt++) {
                int colg = ks0 + nt*8 + (lane & 3)*2;
                if (colg     > rg0) sc[nt][0] = -1e30f;
                if (colg + 1 > rg0) sc[nt][1] = -1e30f;
                if (colg     > rg1) sc[nt][2] = -1e30f;
                if (colg + 1 > rg1) sc[nt][3] = -1e30f;
            }
        }

        // ---- online softmax (per-warp local rows) ----
        float mx0 = -1e30f, mx1 = -1e30f;
#pragma unroll
        for (int nt = 0; nt < 8; nt++) {
            mx0 = fmaxf(mx0, fmaxf(sc[nt][0], sc[nt][1]));
            mx1 = fmaxf(mx1, fmaxf(sc[nt][2], sc[nt][3]));
        }
        mx0 = fmaxf(mx0, __shfl_xor_sync(0xffffffffu, mx0, 1));
        mx0 = fmaxf(mx0, __shfl_xor_sync(0xffffffffu, mx0, 2));
        mx1 = fmaxf(mx1, __shfl_xor_sync(0xffffffffu, mx1, 1));
        mx1 = fmaxf(mx1, __shfl_xor_sync(0xffffffffu, mx1, 2));
        float mn0 = fmaxf(m0, mx0), mn1 = fmaxf(m1, mx1);
        float a0 = __expf(m0 - mn0), a1 = __expf(m1 - mn1);
        m0 = mn0; m1 = mn1;
        float rs0 = 0.f, rs1 = 0.f;
#pragma unroll
        for (int nt = 0; nt < 8; nt++) {
            sc[nt][0] = __expf(sc[nt][0] - mn0); rs0 += sc[nt][0];
            sc[nt][1] = __expf(sc[nt][1] - mn0); rs0 += sc[nt][1];
            sc[nt][2] = __expf(sc[nt][2] - mn1); rs1 += sc[nt][2];
            sc[nt][3] = __expf(sc[nt][3] - mn1); rs1 += sc[nt][3];
        }
        rs0 += __shfl_xor_sync(0xffffffffu, rs0, 1);
        rs0 += __shfl_xor_sync(0xffffffffu, rs0, 2);
        rs1 += __shfl_xor_sync(0xffffffffu, rs1, 1);
        rs1 += __shfl_xor_sync(0xffffffffu, rs1, 2);
        l0 = l0*a0 + rs0;
        l1 = l1*a1 + rs1;
#pragma unroll
        for (int nt = 0; nt < 16; nt++) {
            oc[nt][0] *= a0; oc[nt][1] *= a0;
            oc[nt][2] *= a1; oc[nt][3] *= a1;
        }

        // ---- O += P V (split-bf16, 3 products) ----
#pragma unroll
        for (int kp = 0; kp < 4; kp++) {
            uint32_t ph[4], pl[4];
            {
                float p0 = sc[2*kp][0],  p1 = sc[2*kp][1];
                float p2 = sc[2*kp][2],  p3 = sc[2*kp][3];
                float p4 = sc[2*kp+1][0], p5 = sc[2*kp+1][1];
                float p6 = sc[2*kp+1][2], p7 = sc[2*kp+1][3];
                ph[0] = pack_bf16x2(p0, p1);
                ph[1] = pack_bf16x2(p2, p3);
                ph[2] = pack_bf16x2(p4, p5);
                ph[3] = pack_bf16x2(p6, p7);
                __nv_bfloat162* hp;
                hp = reinterpret_cast<__nv_bfloat162*>(&ph[0]);
                pl[0] = pack_bf16x2(p0 - __bfloat162float(hp->x), p1 - __bfloat162float(hp->y));
                hp = reinterpret_cast<__nv_bfloat162*>(&ph[1]);
                pl[1] = pack_bf16x2(p2 - __bfloat162float(hp->x), p3 - __bfloat162float(hp->y));
                hp = reinterpret_cast<__nv_bfloat162*>(&ph[2]);
                pl[2] = pack_bf16x2(p4 - __bfloat162float(hp->x), p5 - __bfloat162float(hp->y));
                hp = reinterpret_cast<__nv_bfloat162*>(&ph[3]);
                pl[3] = pack_bf16x2(p6 - __bfloat162float(hp->x), p7 - __bfloat162float(hp->y));
            }
#pragma unroll
            for (int ng = 0; ng < 8; ng++) {
                int ch = ng >> 2;
                uint32_t n0 = (uint32_t)((ng & 3)*16) + ((lane >> 4) << 3);
                uint32_t krow = (uint32_t)(kp*16) + (lane & 15);
                uint32_t off = SWZ(krow*128u + n0*2u);
                uint32_t vh[4], vl[4];
                ldmatrix_x4_trans(vh, sb + FL_VH + ch*8192 + off);
                ldmatrix_x4_trans(vl, sb + FL_VL + ch*8192 + off);
                mma_bf16(oc[ng*2],   ph, vh[0], vh[1]);
                mma_bf16(oc[ng*2],   ph, vl[0], vl[1]);
                mma_bf16(oc[ng*2],   pl, vh[0], vh[1]);
                mma_bf16(oc[ng*2+1], ph, vh[2], vh[3]);
                mma_bf16(oc[ng*2+1], ph, vl[2], vl[3]);
                mma_bf16(oc[ng*2+1], pl, vh[2], vh[3]);
            }
        }
    }

    // ---- epilogue ----
    float inv0 = 1.f / l0, inv1 = 1.f / l1;
    int row0 = bb + s0 + wrow + (lane >> 2);
    int row1 = row0 + 8;
#pragma unroll
    for (int nt = 0; nt < 16; nt++) {
        int col = h*128 + nt*8 + (lane & 3)*2;
        *reinterpret_cast<float2*>(att + (size_t)row0*2048 + col) =
            make_float2(oc[nt][0]*inv0, oc[nt][1]*inv0);
        *reinterpret_cast<float2*>(att + (size_t)row1*2048 + col) =
            make_float2(oc[nt][2]*inv1, oc[nt][3]*inv1);
    }
}

// ---------------- host launcher ----------------
extern "C" void kernel_launch(void* const* d_in, const int* in_sizes, int n_in,
                              void* d_out, int out_size)
{
    const float* x      = (const float*)d_in[0];
    const float* wqa    = (const float*)d_in[1];
    const float* wqa_b  = (const float*)d_in[2];
    const float* qnw    = (const float*)d_in[3];
    const float* wqb    = (const float*)d_in[4];
    const float* wqb_b  = (const float*)d_in[5];
    const float* wkva   = (const float*)d_in[6];
    const float* wkva_b = (const float*)d_in[7];
    const float* kvnw   = (const float*)d_in[8];
    const float* wkvb   = (const float*)d_in[9];
    const float* wkvb_b = (const float*)d_in[10];
    const float* wo     = (const float*)d_in[11];
    const float* wo_b   = (const float*)d_in[12];
    float* out = (float*)d_out;

    float *qa, *qbp, *kva, *kvb, *att;
    cudaGetSymbolAddress((void**)&qa,  g_qa);
    cudaGetSymbolAddress((void**)&qbp, g_qb);
    cudaGetSymbolAddress((void**)&kva, g_kva);
    cudaGetSymbolAddress((void**)&kvb, g_kvb);
    cudaGetSymbolAddress((void**)&att, g_att);

    cudaFuncSetAttribute(flash_mma, cudaFuncAttributeMaxDynamicSharedMemorySize, FL_SMEM + 128);
    cudaFuncSetAttribute(gemm_mma, cudaFuncAttributeMaxDynamicSharedMemorySize, GM_SMEM);

    dim3 t256(256);

    gemm_mma<<<dim3(QLORA/128, ROWS/128), t256, GM_SMEM>>>(x, DIMX, wqa, DIMX, wqa_b, qa, QLORA, QLORA, DIMX);
    rmsnorm_kernel<<<ROWS, t256>>>(qa, qa, qnw, QLORA, QLORA, QLORA);
    gemm_mma<<<dim3(3072/128, ROWS/128), t256, GM_SMEM>>>(qa, QLORA, wqb, QLORA, wqb_b, qbp, 3072, 3072, QLORA);
    gemm_mma<<<dim3((576+127)/128, ROWS/128), t256, GM_SMEM>>>(x, DIMX, wkva, DIMX, wkva_b, kva, 576, 576, DIMX);
    rope_kernel<<<ROWS, t256>>>(qbp, kva);
    rmsnorm_kernel<<<ROWS, t256>>>(kva, kva, kvnw, KVLORA, 576, 576);
    gemm_mma<<<dim3(4096/128, ROWS/128), t256, GM_SMEM>>>(kva, 576, wkvb, KVLORA, wkvb_b, kvb, 4096, 4096, KVLORA);
    flash_mma<<<dim3(SEQL/128, NHEADS, BSZ), t256, FL_SMEM + 128>>>(qbp, kvb, kva, att);
    gemm_mma<<<dim3(2048/128, ROWS/128), t256, GM_SMEM>>>(att, 2048, wo, 2048, wo_b, out, 2048, 2048, DIMX);
}

// round 5
// speedup vs baseline: 4.0523x; 1.1000x over previous
#include <cuda_runtime.h>
#include <cuda_bf16.h>
#include <cstdint>
#include <math.h>

#define SEQL   2048
#define BSZ    2
#define ROWS   (BSZ*SEQL)          // 4096
#define DIMX   2048
#define QLORA  1536
#define KVLORA 512
#define NHEADS 16
#define QKHD   192
#define NOPE_D 128
#define ROPE_D 64
#define VHD    128

// ---------------- scratch (static device globals; no allocation) ----------------
__device__ float g_qa [ROWS*QLORA];                 // fp32 intermediates
__device__ float g_qb [ROWS*(NHEADS*QKHD)];
__device__ float g_kva[ROWS*(KVLORA+ROPE_D)];
__device__ float g_kvb[ROWS*(NHEADS*(NOPE_D+VHD))];

// bf16 hi/lo planar operand buffers
__device__ __nv_bfloat16 g_xh  [ROWS*DIMX],   g_xl  [ROWS*DIMX];
__device__ __nv_bfloat16 g_qah [ROWS*QLORA],  g_qal [ROWS*QLORA];
__device__ __nv_bfloat16 g_kvch[ROWS*KVLORA], g_kvcl[ROWS*KVLORA];
__device__ __nv_bfloat16 g_atth[ROWS*2048],   g_attl[ROWS*2048];
__device__ __nv_bfloat16 g_wqah[QLORA*DIMX],  g_wqal[QLORA*DIMX];
__device__ __nv_bfloat16 g_wqbh[3072*QLORA],  g_wqbl[3072*QLORA];
__device__ __nv_bfloat16 g_wkvah[576*DIMX],   g_wkval[576*DIMX];
__device__ __nv_bfloat16 g_wkvbh[4096*KVLORA],g_wkvbl[4096*KVLORA];
__device__ __nv_bfloat16 g_woh [DIMX*2048],   g_wol [DIMX*2048];

__device__ __forceinline__ uint32_t smem_to_u32(const void* p) {
    uint32_t a;
    asm("{ .reg .u64 t; cvta.to.shared.u64 t, %1; cvt.u32.u64 %0, t; }" : "=r"(a) : "l"(p));
    return a;
}
#define SWZ(x) ((x) ^ (((x) >> 3) & 0x70))

__device__ __forceinline__ void ldmatrix_x4(uint32_t* r, uint32_t addr) {
    asm volatile("ldmatrix.sync.aligned.m8n8.x4.shared.b16 {%0,%1,%2,%3}, [%4];"
        : "=r"(r[0]), "=r"(r[1]), "=r"(r[2]), "=r"(r[3]) : "r"(addr));
}
__device__ __forceinline__ void ldmatrix_x4_trans(uint32_t* r, uint32_t addr) {
    asm volatile("ldmatrix.sync.aligned.m8n8.x4.trans.shared.b16 {%0,%1,%2,%3}, [%4];"
        : "=r"(r[0]), "=r"(r[1]), "=r"(r[2]), "=r"(r[3]) : "r"(addr));
}
__device__ __forceinline__ void mma_bf16(float* c, const uint32_t* a, uint32_t b0, uint32_t b1) {
    asm volatile(
        "mma.sync.aligned.m16n8k16.row.col.f32.bf16.bf16.f32 "
        "{%0,%1,%2,%3}, {%4,%5,%6,%7}, {%8,%9}, {%0,%1,%2,%3};"
        : "+f"(c[0]), "+f"(c[1]), "+f"(c[2]), "+f"(c[3])
        : "r"(a[0]), "r"(a[1]), "r"(a[2]), "r"(a[3]), "r"(b0), "r"(b1));
}
__device__ __forceinline__ uint32_t pack_bf16x2(float lo, float hi) {
    __nv_bfloat162 h = __floats2bfloat162_rn(lo, hi);
    return *reinterpret_cast<uint32_t*>(&h);
}
__device__ __forceinline__ void cp_async16(uint32_t dst, const void* src) {
    asm volatile("cp.async.cg.shared.global [%0], [%1], 16;" :: "r"(dst), "l"(src));
}
#define CP_COMMIT() asm volatile("cp.async.commit_group;" ::: "memory")
#define CP_WAIT1()  asm volatile("cp.async.wait_group 1;" ::: "memory")

// ---------------- fp32 -> bf16 hi/lo planar converter ----------------
__global__ __launch_bounds__(256)
void cvt_hilo(const float* __restrict__ s, __nv_bfloat16* __restrict__ hi,
              __nv_bfloat16* __restrict__ lo, int n)
{
    int i = (blockIdx.x * 256 + threadIdx.x) * 4;
    if (i >= n) return;
    float4 v = *reinterpret_cast<const float4*>(s + i);
    __nv_bfloat162 h01 = __floats2bfloat162_rn(v.x, v.y);
    __nv_bfloat162 h23 = __floats2bfloat162_rn(v.z, v.w);
    __nv_bfloat162 l01 = __floats2bfloat162_rn(v.x - __bfloat162float(h01.x),
                                               v.y - __bfloat162float(h01.y));
    __nv_bfloat162 l23 = __floats2bfloat162_rn(v.z - __bfloat162float(h23.x),
                                               v.w - __bfloat162float(h23.y));
    *reinterpret_cast<uint2*>(hi + i) =
        make_uint2(*reinterpret_cast<uint32_t*>(&h01), *reinterpret_cast<uint32_t*>(&h23));
    *reinterpret_cast<uint2*>(lo + i) =
        make_uint2(*reinterpret_cast<uint32_t*>(&l01), *reinterpret_cast<uint32_t*>(&l23));
}

// ============ cp.async 3-stage split-bf16 HMMA GEMM ============
// C[M,N] = (Ah+Al)[M,K] @ (Bh+Bl)[N,K]^T + bias  (3 products)
// CTA 128x128, K-tile 64, 8 warps 4x2, stage = Ah|Al|Bh|Bl 16KB each = 64KB.
#define GB_STAGE 65536
#define GB_SMEM  (3*GB_STAGE + 128)

__global__ __launch_bounds__(256, 1)
void gemm_bf(const __nv_bfloat16* __restrict__ Ah, const __nv_bfloat16* __restrict__ Al, int lda,
             const __nv_bfloat16* __restrict__ Bh, const __nv_bfloat16* __restrict__ Bl, int ldw,
             const float* __restrict__ bias,
             float* __restrict__ C, int ldc,
             int Nn, int K)
{
    extern __shared__ char smraw[];
    uint32_t sb0 = smem_to_u32(smraw);
    uint32_t sb = (sb0 + 127u) & ~127u;

    const int tid  = threadIdx.x;
    const int lane = tid & 31;
    const int wid  = tid >> 5;
    const int bm = blockIdx.y * 128;
    const int bn = blockIdx.x * 128;
    const int wm = (wid & 3) * 32;
    const int wn = (wid >> 2) * 64;
    const int nk = K >> 6;

    float acc[2][8][4];
#pragma unroll
    for (int mt = 0; mt < 2; mt++)
#pragma unroll
        for (int nt = 0; nt < 8; nt++)
#pragma unroll
            for (int q = 0; q < 4; q++) acc[mt][nt][q] = 0.f;

    // ---- issue helper pattern: 16 chunks/thread, plane = i>>2 ----
    // plane 0=Ah 1=Al 2=Bh 3=Bl; idx within plane = (i&3)*256 + tid
#define GB_ISSUE(kt_) do {                                                      \
        const uint32_t stb = sb + (uint32_t)((kt_) % 3) * GB_STAGE;             \
        const int k0_ = (kt_) << 6;                                             \
        _Pragma("unroll")                                                       \
        for (int i = 0; i < 16; i++) {                                          \
            const int plane = i >> 2;                                           \
            const int idx = ((i & 3) << 8) + tid;                               \
            const int r = idx >> 3;                                             \
            const int c = idx & 7;                                              \
            uint32_t dst = stb + (uint32_t)plane*16384u                         \
                         + SWZ((uint32_t)(r*128 + c*16));                       \
            const __nv_bfloat16* srcp;                                          \
            if (plane == 0)      srcp = Ah + (size_t)(bm + r)*lda + k0_ + c*8;  \
            else if (plane == 1) srcp = Al + (size_t)(bm + r)*lda + k0_ + c*8;  \
            else {                                                              \
                int rr = bn + r; if (rr >= Nn) rr = Nn - 1;                     \
                srcp = (plane == 2 ? Bh : Bl) + (size_t)rr*ldw + k0_ + c*8;     \
            }                                                                   \
            cp_async16(dst, srcp);                                              \
        }                                                                       \
    } while (0)

    // prologue: stages 0 and 1
    GB_ISSUE(0); CP_COMMIT();
    if (nk > 1) { GB_ISSUE(1); }
    CP_COMMIT();

    for (int kt = 0; kt < nk; kt++) {
        CP_WAIT1();
        __syncthreads();

        const uint32_t baseA = sb + (uint32_t)(kt % 3) * GB_STAGE;
        const uint32_t baseB = baseA + 32768u;
#pragma unroll
        for (int k16 = 0; k16 < 4; k16++) {
            uint32_t ah[2][4], al[2][4];
#pragma unroll
            for (int mt = 0; mt < 2; mt++) {
                uint32_t row = wm + mt*16 + (lane & 15);
                uint32_t off = SWZ(row*128u + (uint32_t)(k16*32) + ((lane >> 4) << 4));
                ldmatrix_x4(ah[mt], baseA + off);
                ldmatrix_x4(al[mt], baseA + 16384u + off);
            }
            uint32_t bh[16], bl[16];
#pragma unroll
            for (int ng = 0; ng < 4; ng++) {
                uint32_t nrow = wn + ng*16 + ((lane >> 4) << 3) + (lane & 7);
                uint32_t off = SWZ(nrow*128u + (uint32_t)(k16*32) + (((lane >> 3) & 1) << 4));
                ldmatrix_x4(&bh[ng*4], baseB + off);
                ldmatrix_x4(&bl[ng*4], baseB + 16384u + off);
            }
#pragma unroll
            for (int mt = 0; mt < 2; mt++)
#pragma unroll
                for (int nt = 0; nt < 8; nt++) {
                    mma_bf16(acc[mt][nt], ah[mt], bh[nt*2], bh[nt*2+1]);
                    mma_bf16(acc[mt][nt], ah[mt], bl[nt*2], bl[nt*2+1]);
                    mma_bf16(acc[mt][nt], al[mt], bh[nt*2], bh[nt*2+1]);
                }
        }
        __syncthreads();
        if (kt + 2 < nk) { GB_ISSUE(kt + 2); }
        CP_COMMIT();
    }

    // ---- epilogue ----
#pragma unroll
    for (int nt = 0; nt < 8; nt++) {
        int col = bn + wn + nt*8 + (lane & 3)*2;
        if (col >= Nn) continue;
        float bx = bias[col], by = bias[col+1];
#pragma unroll
        for (int mt = 0; mt < 2; mt++) {
            int row = bm + wm + mt*16 + (lane >> 2);
            *reinterpret_cast<float2*>(C + (size_t)row*ldc + col) =
                make_float2(acc[mt][nt][0] + bx, acc[mt][nt][1] + by);
            *reinterpret_cast<float2*>(C + (size_t)(row+8)*ldc + col) =
                make_float2(acc[mt][nt][2] + bx, acc[mt][nt][3] + by);
        }
    }
#undef GB_ISSUE
}

// ---------------- RMSNorm -> bf16 hi/lo planar ----------------
__global__ __launch_bounds__(256)
void rmsnorm_hilo(const float* __restrict__ src,
                  __nv_bfloat16* __restrict__ hi, __nv_bfloat16* __restrict__ lo,
                  const float* __restrict__ w, int width, int sstride, int dstride)
{
    int row = blockIdx.x;
    const float* s = src + (size_t)row * sstride;

    float ss = 0.f;
    for (int c = threadIdx.x; c < width; c += blockDim.x) { float v = s[c]; ss += v*v; }

    __shared__ float red[8];
#pragma unroll
    for (int off = 16; off; off >>= 1) ss += __shfl_xor_sync(0xffffffffu, ss, off);
    int warp = threadIdx.x >> 5;
    if ((threadIdx.x & 31) == 0) red[warp] = ss;
    __syncthreads();
    if (warp == 0) {
        float v = (threadIdx.x < 8) ? red[threadIdx.x] : 0.f;
#pragma unroll
        for (int off = 4; off; off >>= 1) v += __shfl_xor_sync(0xffffffffu, v, off);
        if (threadIdx.x == 0) red[0] = v;
    }
    __syncthreads();
    float scale = rsqrtf(red[0] / (float)width + 1e-6f);
    __nv_bfloat16* dh = hi + (size_t)row * dstride;
    __nv_bfloat16* dl = lo + (size_t)row * dstride;
    for (int c = threadIdx.x; c < width; c += blockDim.x) {
        float v = s[c] * scale * w[c];
        __nv_bfloat16 hv = __float2bfloat16_rn(v);
        dh[c] = hv;
        dl[c] = __float2bfloat16_rn(v - __bfloat162float(hv));
    }
}

// ---------------- RoPE ----------------
__global__ __launch_bounds__(256)
void rope_kernel(float* __restrict__ qb, float* __restrict__ kva)
{
    int row = blockIdx.x;
    int s = row & (SEQL - 1);
    for (int p = threadIdx.x; p < 544; p += blockDim.x) {
        int d = p & 31;
        float ang = (float)s * powf(10000.f, -(float)d * (1.f/32.f));
        float sn, c;
        sincosf(ang, &sn, &c);
        float* base;
        if (p < 512) {
            int hh = p >> 5;
            base = qb + (size_t)row*(NHEADS*QKHD) + hh*QKHD + NOPE_D;
        } else {
            base = kva + (size_t)row*(KVLORA+ROPE_D) + KVLORA;
        }
        float x1 = base[d], x2 = base[d+32];
        base[d]    = x1*c - x2*sn;
        base[d+32] = x2*c + x1*sn;
    }
}

// ============ Flash attention via mma.sync (split-bf16) ============
#define FL_QH 0
#define FL_QL 49152
#define FL_KH 98304
#define FL_KL 122880
#define FL_VH 147456
#define FL_VL 163840
#define FL_SMEM 180224

__global__ __launch_bounds__(256, 1)
void flash_mma(const float* __restrict__ qb,
               const float* __restrict__ kvb,
               const float* __restrict__ kva,
               __nv_bfloat16* __restrict__ atth,
               __nv_bfloat16* __restrict__ attl)
{
    extern __shared__ char smraw[];
    uint32_t sb0 = smem_to_u32(smraw);
    uint32_t sb = (sb0 + 127u) & ~127u;
    char* smp = smraw + (sb - sb0);

    const int qt = blockIdx.x;
    const int h  = blockIdx.y;
    const int b  = blockIdx.z;
    const int s0 = qt * 128;
    const int bb = b * SEQL;
    const int tid  = threadIdx.x;
    const int lane = tid & 31;
    const int wid  = tid >> 5;
    const int wrow = wid * 16;
    const float scale = 0.07216878364870323f;

#pragma unroll
    for (int i = 0; i < 24; i++) {
        int idx = tid + i*256;
        int row = idx / 48;
        int d = (idx - row*48) * 4;
        float4 v = *reinterpret_cast<const float4*>(
            qb + (size_t)(bb + s0 + row)*3072 + h*192 + d);
        v.x *= scale; v.y *= scale; v.z *= scale; v.w *= scale;
        int ch = d >> 6, dc = d & 63;
        uint32_t off = SWZ((uint32_t)(row*128 + dc*2));
        __nv_bfloat162 h01 = __floats2bfloat162_rn(v.x, v.y);
        __nv_bfloat162 h23 = __floats2bfloat162_rn(v.z, v.w);
        __nv_bfloat162 l01 = __floats2bfloat162_rn(v.x - __bfloat162float(h01.x),
                                                   v.y - __bfloat162float(h01.y));
        __nv_bfloat162 l23 = __floats2bfloat162_rn(v.z - __bfloat162float(h23.x),
                                                   v.w - __bfloat162float(h23.y));
        *reinterpret_cast<uint2*>(smp + FL_QH + ch*16384 + off) =
            make_uint2(*reinterpret_cast<uint32_t*>(&h01), *reinterpret_cast<uint32_t*>(&h23));
        *reinterpret_cast<uint2*>(smp + FL_QL + ch*16384 + off) =
            make_uint2(*reinterpret_cast<uint32_t*>(&l01), *reinterpret_cast<uint32_t*>(&l23));
    }

    float oc[16][4];
#pragma unroll
    for (int nt = 0; nt < 16; nt++)
#pragma unroll
        for (int q = 0; q < 4; q++) oc[nt][q] = 0.f;
    float m0 = -1e30f, m1 = -1e30f, l0 = 0.f, l1 = 0.f;

    const int rg0 = s0 + wrow + (lane >> 2);
    const int rg1 = rg0 + 8;
    const int nkt = 2*qt + 2;

    for (int kt = 0; kt < nkt; kt++) {
        if (kt > 0) __syncthreads();
        const int ks0 = kt * 64;

#pragma unroll
        for (int i = 0; i < 8; i++) {
            int idx = tid + i*256;
            int row = idx >> 5;
            int d = (idx & 31) * 4;
            float4 v = *reinterpret_cast<const float4*>(
                kvb + (size_t)(bb + ks0 + row)*4096 + h*256 + d);
            int ch = d >> 6, dc = d & 63;
            uint32_t off = SWZ((uint32_t)(row*128 + dc*2));
            __nv_bfloat162 h01 = __floats2bfloat162_rn(v.x, v.y);
            __nv_bfloat162 h23 = __floats2bfloat162_rn(v.z, v.w);
            __nv_bfloat162 l01 = __floats2bfloat162_rn(v.x - __bfloat162float(h01.x),
                                                       v.y - __bfloat162float(h01.y));
            __nv_bfloat162 l23 = __floats2bfloat162_rn(v.z - __bfloat162float(h23.x),
                                                       v.w - __bfloat162float(h23.y));
            *reinterpret_cast<uint2*>(smp + FL_KH + ch*8192 + off) =
                make_uint2(*reinterpret_cast<uint32_t*>(&h01), *reinterpret_cast<uint32_t*>(&h23));
            *reinterpret_cast<uint2*>(smp + FL_KL + ch*8192 + off) =
                make_uint2(*reinterpret_cast<uint32_t*>(&l01), *reinterpret_cast<uint32_t*>(&l23));
        }
#pragma unroll
        for (int i = 0; i < 4; i++) {
            int idx = tid + i*256;
            int row = idx >> 4;
            int d2 = (idx & 15) * 4;
            float4 v = *reinterpret_cast<const float4*>(
                kva + (size_t)(bb + ks0 + row)*576 + 512 + d2);
            uint32_t off = SWZ((uint32_t)(row*128 + d2*2));
            __nv_bfloat162 h01 = __floats2bfloat162_rn(v.x, v.y);
            __nv_bfloat162 h23 = __floats2bfloat162_rn(v.z, v.w);
            __nv_bfloat162 l01 = __floats2bfloat162_rn(v.x - __bfloat162float(h01.x),
                                                       v.y - __bfloat162float(h01.y));
            __nv_bfloat162 l23 = __floats2bfloat162_rn(v.z - __bfloat162float(h23.x),
                                                       v.w - __bfloat162float(h23.y));
            *reinterpret_cast<uint2*>(smp + FL_KH + 2*8192 + off) =
                make_uint2(*reinterpret_cast<uint32_t*>(&h01), *reinterpret_cast<uint32_t*>(&h23));
            *reinterpret_cast<uint2*>(smp + FL_KL + 2*8192 + off) =
                make_uint2(*reinterpret_cast<uint32_t*>(&l01), *reinterpret_cast<uint32_t*>(&l23));
        }
#pragma unroll
        for (int i = 0; i < 8; i++) {
            int idx = tid + i*256;
            int row = idx >> 5;
            int d = (idx & 31) * 4;
            float4 v = *reinterpret_cast<const float4*>(
                kvb + (size_t)(bb + ks0 + row)*4096 + h*256 + 128 + d);
            int ch = d >> 6, dc = d & 63;
            uint32_t off = SWZ((uint32_t)(row*128 + dc*2));
            __nv_bfloat162 h01 = __floats2bfloat162_rn(v.x, v.y);
            __nv_bfloat162 h23 = __floats2bfloat162_rn(v.z, v.w);
            __nv_bfloat162 l01 = __floats2bfloat162_rn(v.x - __bfloat162float(h01.x),
                                                       v.y - __bfloat162float(h01.y));
            __nv_bfloat162 l23 = __floats2bfloat162_rn(v.z - __bfloat162float(h23.x),
                                                       v.w - __bfloat162float(h23.y));
            *reinterpret_cast<uint2*>(smp + FL_VH + ch*8192 + off) =
                make_uint2(*reinterpret_cast<uint32_t*>(&h01), *reinterpret_cast<uint32_t*>(&h23));
            *reinterpret_cast<uint2*>(smp + FL_VL + ch*8192 + off) =
                make_uint2(*reinterpret_cast<uint32_t*>(&l01), *reinterpret_cast<uint32_t*>(&l23));
        }
        __syncthreads();

        if (ks0 > s0 + wrow + 15) continue;

        float sc[8][4];
#pragma unroll
        for (int nt = 0; nt < 8; nt++)
#pragma unroll
            for (int q = 0; q < 4; q++) sc[nt][q] = 0.f;

#pragma unroll
        for (int ks = 0; ks < 12; ks++) {
            int ch = ks >> 2;
            uint32_t kb = (uint32_t)((ks & 3) * 32);
            uint32_t ah[4], al[4];
            {
                uint32_t row = wrow + (lane & 15);
                uint32_t off = SWZ(row*128u + kb + ((lane >> 4) << 4));
                ldmatrix_x4(ah, sb + FL_QH + ch*16384 + off);
                ldmatrix_x4(al, sb + FL_QL + ch*16384 + off);
            }
            uint32_t bh[16], bl[16];
#pragma unroll
            for (int ng = 0; ng < 4; ng++) {
                uint32_t nrow = ng*16 + ((lane >> 4) << 3) + (lane & 7);
                uint32_t off = SWZ(nrow*128u + kb + (((lane >> 3) & 1) << 4));
                ldmatrix_x4(&bh[ng*4], sb + FL_KH + ch*8192 + off);
                ldmatrix_x4(&bl[ng*4], sb + FL_KL + ch*8192 + off);
            }
#pragma unroll
            for (int nt = 0; nt < 8; nt++) {
                mma_bf16(sc[nt], ah, bh[nt*2], bh[nt*2+1]);
                mma_bf16(sc[nt], ah, bl[nt*2], bl[nt*2+1]);
                mma_bf16(sc[nt], al, bh[nt*2], bh[nt*2+1]);
            }
        }

        if (ks0 + 63 > s0 + wrow) {
#pragma unroll
            for (int nt = 0; nt < 8; nt++) {
                int colg = ks0 + nt*8 + (lane & 3)*2;
                if (colg     > rg0) sc[nt][0] = -1e30f;
                if (colg + 1 > rg0) sc[nt][1] = -1e30f;
                if (colg     > rg1) sc[nt][2] = -1e30f;
                if (colg + 1 > rg1) sc[nt][3] = -1e30f;
            }
        }

        float mx0 = -1e30f, mx1 = -1e30f;
#pragma unroll
        for (int nt = 0; nt < 8; nt++) {
            mx0 = fmaxf(mx0, fmaxf(sc[nt][0], sc[nt][1]));
            mx1 = fmaxf(mx1, fmaxf(sc[nt][2], sc[nt][3]));
        }
        mx0 = fmaxf(mx0, __shfl_xor_sync(0xffffffffu, mx0, 1));
        mx0 = fmaxf(mx0, __shfl_xor_sync(0xffffffffu, mx0, 2));
        mx1 = fmaxf(mx1, __shfl_xor_sync(0xffffffffu, mx1, 1));
        mx1 = fmaxf(mx1, __shfl_xor_sync(0xffffffffu, mx1, 2));
        float mn0 = fmaxf(m0, mx0), mn1 = fmaxf(m1, mx1);
        float a0 = __expf(m0 - mn0), a1 = __expf(m1 - mn1);
        m0 = mn0; m1 = mn1;
        float rs0 = 0.f, rs1 = 0.f;
#pragma unroll
        for (int nt = 0; nt < 8; nt++) {
            sc[nt][0] = __expf(sc[nt][0] - mn0); rs0 += sc[nt][0];
            sc[nt][1] = __expf(sc[nt][1] - mn0); rs0 += sc[nt][1];
            sc[nt][2] = __expf(sc[nt][2] - mn1); rs1 += sc[nt][2];
            sc[nt][3] = __expf(sc[nt][3] - mn1); rs1 += sc[nt][3];
        }
        rs0 += __shfl_xor_sync(0xffffffffu, rs0, 1);
        rs0 += __shfl_xor_sync(0xffffffffu, rs0, 2);
        rs1 += __shfl_xor_sync(0xffffffffu, rs1, 1);
        rs1 += __shfl_xor_sync(0xffffffffu, rs1, 2);
        l0 = l0*a0 + rs0;
        l1 = l1*a1 + rs1;
#pragma unroll
        for (int nt = 0; nt < 16; nt++) {
            oc[nt][0] *= a0; oc[nt][1] *= a0;
            oc[nt][2] *= a1; oc[nt][3] *= a1;
        }

#pragma unroll
        for (int kp = 0; kp < 4; kp++) {
            uint32_t ph[4], pl[4];
            {
                float p0 = sc[2*kp][0],  p1 = sc[2*kp][1];
                float p2 = sc[2*kp][2],  p3 = sc[2*kp][3];
                float p4 = sc[2*kp+1][0], p5 = sc[2*kp+1][1];
                float p6 = sc[2*kp+1][2], p7 = sc[2*kp+1][3];
                ph[0] = pack_bf16x2(p0, p1);
                ph[1] = pack_bf16x2(p2, p3);
                ph[2] = pack_bf16x2(p4, p5);
                ph[3] = pack_bf16x2(p6, p7);
                __nv_bfloat162* hp;
                hp = reinterpret_cast<__nv_bfloat162*>(&ph[0]);
                pl[0] = pack_bf16x2(p0 - __bfloat162float(hp->x), p1 - __bfloat162float(hp->y));
                hp = reinterpret_cast<__nv_bfloat162*>(&ph[1]);
                pl[1] = pack_bf16x2(p2 - __bfloat162float(hp->x), p3 - __bfloat162float(hp->y));
                hp = reinterpret_cast<__nv_bfloat162*>(&ph[2]);
                pl[2] = pack_bf16x2(p4 - __bfloat162float(hp->x), p5 - __bfloat162float(hp->y));
                hp = reinterpret_cast<__nv_bfloat162*>(&ph[3]);
                pl[3] = pack_bf16x2(p6 - __bfloat162float(hp->x), p7 - __bfloat162float(hp->y));
            }
#pragma unroll
            for (int ng = 0; ng < 8; ng++) {
                int ch = ng >> 2;
                uint32_t n0 = (uint32_t)((ng & 3)*16) + ((lane >> 4) << 3);
                uint32_t krow = (uint32_t)(kp*16) + (lane & 15);
                uint32_t off = SWZ(krow*128u + n0*2u);
                uint32_t vh[4], vl[4];
                ldmatrix_x4_trans(vh, sb + FL_VH + ch*8192 + off);
                ldmatrix_x4_trans(vl, sb + FL_VL + ch*8192 + off);
                mma_bf16(oc[ng*2],   ph, vh[0], vh[1]);
                mma_bf16(oc[ng*2],   ph, vl[0], vl[1]);
                mma_bf16(oc[ng*2],   pl, vh[0], vh[1]);
                mma_bf16(oc[ng*2+1], ph, vh[2], vh[3]);
                mma_bf16(oc[ng*2+1], ph, vl[2], vl[3]);
                mma_bf16(oc[ng*2+1], pl, vh[2], vh[3]);
            }
        }
    }

    // ---- epilogue: write att directly as bf16 hi/lo ----
    float inv0 = 1.f / l0, inv1 = 1.f / l1;
    int row0 = bb + s0 + wrow + (lane >> 2);
    int row1 = row0 + 8;
#pragma unroll
    for (int nt = 0; nt < 16; nt++) {
        int col = h*128 + nt*8 + (lane & 3)*2;
        float o0 = oc[nt][0]*inv0, o1 = oc[nt][1]*inv0;
        float o2 = oc[nt][2]*inv1, o3 = oc[nt][3]*inv1;
        uint32_t h0 = pack_bf16x2(o0, o1);
        __nv_bfloat162 hv0 = *reinterpret_cast<__nv_bfloat162*>(&h0);
        uint32_t l0p = pack_bf16x2(o0 - __bfloat162float(hv0.x), o1 - __bfloat162float(hv0.y));
        uint32_t h1 = pack_bf16x2(o2, o3);
        __nv_bfloat162 hv1 = *reinterpret_cast<__nv_bfloat162*>(&h1);
        uint32_t l1p = pack_bf16x2(o2 - __bfloat162float(hv1.x), o3 - __bfloat162float(hv1.y));
        *reinterpret_cast<uint32_t*>(atth + (size_t)row0*2048 + col) = h0;
        *reinterpret_cast<uint32_t*>(attl + (size_t)row0*2048 + col) = l0p;
        *reinterpret_cast<uint32_t*>(atth + (size_t)row1*2048 + col) = h1;
        *reinterpret_cast<uint32_t*>(attl + (size_t)row1*2048 + col) = l1p;
    }
}

// ---------------- host launcher ----------------
extern "C" void kernel_launch(void* const* d_in, const int* in_sizes, int n_in,
                              void* d_out, int out_size)
{
    const float* x      = (const float*)d_in[0];
    const float* wqa    = (const float*)d_in[1];
    const float* wqa_b  = (const float*)d_in[2];
    const float* qnw    = (const float*)d_in[3];
    const float* wqb    = (const float*)d_in[4];
    const float* wqb_b  = (const float*)d_in[5];
    const float* wkva   = (const float*)d_in[6];
    const float* wkva_b = (const float*)d_in[7];
    const float* kvnw   = (const float*)d_in[8];
    const float* wkvb   = (const float*)d_in[9];
    const float* wkvb_b = (const float*)d_in[10];
    const float* wo     = (const float*)d_in[11];
    const float* wo_b   = (const float*)d_in[12];
    float* out = (float*)d_out;

    float *qa, *qbp, *kva, *kvb;
    cudaGetSymbolAddress((void**)&qa,  g_qa);
    cudaGetSymbolAddress((void**)&qbp, g_qb);
    cudaGetSymbolAddress((void**)&kva, g_kva);
    cudaGetSymbolAddress((void**)&kvb, g_kvb);
    __nv_bfloat16 *xh,*xl,*qah,*qal,*kvch,*kvcl,*atth,*attl;
    __nv_bfloat16 *wqah,*wqal,*wqbh,*wqbl,*wkvah,*wkval,*wkvbh,*wkvbl,*woh,*wol;
    cudaGetSymbolAddress((void**)&xh, g_xh);   cudaGetSymbolAddress((void**)&xl, g_xl);
    cudaGetSymbolAddress((void**)&qah, g_qah); cudaGetSymbolAddress((void**)&qal, g_qal);
    cudaGetSymbolAddress((void**)&kvch, g_kvch); cudaGetSymbolAddress((void**)&kvcl, g_kvcl);
    cudaGetSymbolAddress((void**)&atth, g_atth); cudaGetSymbolAddress((void**)&attl, g_attl);
    cudaGetSymbolAddress((void**)&wqah, g_wqah); cudaGetSymbolAddress((void**)&wqal, g_wqal);
    cudaGetSymbolAddress((void**)&wqbh, g_wqbh); cudaGetSymbolAddress((void**)&wqbl, g_wqbl);
    cudaGetSymbolAddress((void**)&wkvah, g_wkvah); cudaGetSymbolAddress((void**)&wkval, g_wkval);
    cudaGetSymbolAddress((void**)&wkvbh, g_wkvbh); cudaGetSymbolAddress((void**)&wkvbl, g_wkvbl);
    cudaGetSymbolAddress((void**)&woh, g_woh); cudaGetSymbolAddress((void**)&wol, g_wol);

    cudaFuncSetAttribute(flash_mma, cudaFuncAttributeMaxDynamicSharedMemorySize, FL_SMEM + 128);
    cudaFuncSetAttribute(gemm_bf, cudaFuncAttributeMaxDynamicSharedMemorySize, GB_SMEM);

    dim3 t256(256);

    // convert weights + x to bf16 hi/lo
    cvt_hilo<<<(QLORA*DIMX)/1024, t256>>>(wqa, wqah, wqal, QLORA*DIMX);
    cvt_hilo<<<(3072*QLORA)/1024, t256>>>(wqb, wqbh, wqbl, 3072*QLORA);
    cvt_hilo<<<(576*DIMX)/1024, t256>>>(wkva, wkvah, wkval, 576*DIMX);
    cvt_hilo<<<(4096*KVLORA)/1024, t256>>>(wkvb, wkvbh, wkvbl, 4096*KVLORA);
    cvt_hilo<<<(DIMX*2048)/1024, t256>>>(wo, woh, wol, DIMX*2048);
    cvt_hilo<<<(ROWS*DIMX)/1024, t256>>>(x, xh, xl, ROWS*DIMX);

    // 1. q_a = x @ wq_a^T + b
    gemm_bf<<<dim3(QLORA/128, ROWS/128), t256, GB_SMEM>>>(xh, xl, DIMX, wqah, wqal, DIMX, wqa_b, qa, QLORA, QLORA, DIMX);
    // 2. rmsnorm -> bf16 hi/lo
    rmsnorm_hilo<<<ROWS, t256>>>(qa, qah, qal, qnw, QLORA, QLORA, QLORA);
    // 3. q_b
    gemm_bf<<<dim3(3072/128, ROWS/128), t256, GB_SMEM>>>(qah, qal, QLORA, wqbh, wqbl, QLORA, wqb_b, qbp, 3072, 3072, QLORA);
    // 4. kv_a
    gemm_bf<<<dim3((576+127)/128, ROWS/128), t256, GB_SMEM>>>(xh, xl, DIMX, wkvah, wkval, DIMX, wkva_b, kva, 576, 576, DIMX);
    // 5. RoPE
    rope_kernel<<<ROWS, t256>>>(qbp, kva);
    // 6. kv_c rmsnorm -> compact bf16 hi/lo (stride 512)
    rmsnorm_hilo<<<ROWS, t256>>>(kva, kvch, kvcl, kvnw, KVLORA, 576, KVLORA);
    // 7. kvb
    gemm_bf<<<dim3(4096/128, ROWS/128), t256, GB_SMEM>>>(kvch, kvcl, KVLORA, wkvbh, wkvbl, KVLORA, wkvb_b, kvb, 4096, 4096, KVLORA);
    // 8. flash -> att bf16 hi/lo
    flash_mma<<<dim3(SEQL/128, NHEADS, BSZ), t256, FL_SMEM + 128>>>(qbp, kvb, kva, atth, attl);
    // 9. out
    gemm_bf<<<dim3(2048/128, ROWS/128), t256, GB_SMEM>>>(atth, attl, 2048, woh, wol, 2048, wo_b, out, 2048, 2048, DIMX);
}